// round 11
// baseline (speedup 1.0000x reference)
#include <cuda_runtime.h>
#include <math.h>

// ---------------- f32x2 packed-FMA helpers (bitwise = 2x IEEE fp32 FMA) ----
__device__ __forceinline__ unsigned long long f2pack(float x,float y){
  unsigned long long r;
  asm("mov.b64 %0,{%1,%2};":"=l"(r):"r"(__float_as_uint(x)),"r"(__float_as_uint(y)));
  return r;
}
__device__ __forceinline__ void f2unpack(unsigned long long v,float&x,float&y){
  unsigned ux,uy;
  asm("mov.b64 {%0,%1},%2;":"=r"(ux),"=r"(uy):"l"(v));
  x=__uint_as_float(ux); y=__uint_as_float(uy);
}
__device__ __forceinline__ void ffma2(unsigned long long&d,unsigned long long a,unsigned long long b){
  asm("fma.rn.f32x2 %0,%1,%2,%0;":"+l"(d):"l"(a),"l"(b));
}

// ---------------- scratch ----------------
__device__ float g_SESS[128*128];
__device__ int   g_IN1[128*400];
__device__ float g_W0 [128*400];
__device__ int   g_IN2[128*3200];
__device__ float g_W1n[128*3200];
__device__ float g_NG0[128*50*128];
__device__ float g_NG1[128*400*128];
__device__ float g_A0 [128*50*128];
__device__ float g_A1 [128*400*128];
__device__ float g_HL [128*50*128];
__device__ float g_HG [128*50*128];
__device__ float g_NH [128*50*128];
__device__ float g_SEL[128*128];
__device__ float g_SEL2T[128*128];
__device__ float g_LP[128];
__device__ int   g_PR[128];
__device__ int   g_PC[64];

// ---------------- threefry ----------------
__device__ __forceinline__ void tf(unsigned k0,unsigned k1,unsigned x0,unsigned x1,
                                   unsigned&o0,unsigned&o1){
  unsigned ks2=k0^k1^0x1BD11BDAu;
  x0+=k0; x1+=k1;
#define RND(r) {x0+=x1; x1=(x1<<(r))|(x1>>(32-(r))); x1^=x0;}
  RND(13)RND(15)RND(26)RND(6)   x0+=k1;  x1+=ks2+1u;
  RND(17)RND(29)RND(16)RND(24)  x0+=ks2; x1+=k0+2u;
  RND(13)RND(15)RND(26)RND(6)   x0+=k0;  x1+=k1+3u;
  RND(17)RND(29)RND(16)RND(24)  x0+=k1;  x1+=ks2+4u;
  RND(13)RND(15)RND(26)RND(6)   x0+=ks2; x1+=k0+5u;
#undef RND
  o0=x0; o1=x1;
}

__global__ void k_perm(){
  __shared__ unsigned keys[4];
  __shared__ unsigned br[128];
  __shared__ unsigned bc[64];
  int t=threadIdx.x;
  if(t==0){
    unsigned u0,u1,v0,v1,p0,p1,q0,q1;
    tf(0u,42u,0u,2u,u0,u1); tf(0u,42u,1u,3u,v0,v1);
    unsigned kr0=u0,kr1=v0,kc0=u1,kc1=v1;
    tf(kr0,kr1,0u,2u,p0,p1); tf(kr0,kr1,1u,3u,q0,q1);
    keys[0]=p1; keys[1]=q1;
    tf(kc0,kc1,0u,2u,p0,p1); tf(kc0,kc1,1u,3u,q0,q1);
    keys[2]=p1; keys[3]=q1;
  }
  __syncthreads();
  { int j=t&63; unsigned w0,w1;
    tf(keys[0],keys[1],(unsigned)j,(unsigned)(j+64),w0,w1);
    br[t]=(t<64)?w0:w1; }
  if(t<50){ int j=(t<25)?t:t-25; unsigned w0,w1;
    tf(keys[2],keys[3],(unsigned)j,(unsigned)(j+25),w0,w1);
    bc[t]=(t<25)?w0:w1; }
  __syncthreads();
  { unsigned mine=br[t]; int r=0;
    for(int j=0;j<128;j++){ unsigned bj=br[j]; r+=(bj<mine)||(bj==mine&&j<t); }
    g_PR[r]=t; }
  if(t<50){ unsigned mine=bc[t]; int r=0;
    for(int j=0;j<50;j++){ unsigned bj=bc[j]; r+=(bj<mine)||(bj==mine&&j<t); }
    g_PC[r]=t; }
}

// ---------------- prep ----------------
__global__ void k_prep1(const int* __restrict__ inputs,const int* __restrict__ adj_all,
                        const float* __restrict__ num_w){
  int t=blockIdx.x*blockDim.x+threadIdx.x;
  if(t<128*400){
    int b=t/400,m=t%400;
    int node=inputs[b*50+(m>>3)];
    g_IN1[t]=adj_all[node*8+(m&7)];
    g_W0[t]=num_w[node*8+(m&7)];
  }
}
__global__ void k_prep2(const int* __restrict__ adj_all,const float* __restrict__ num_w){
  int t=blockIdx.x*blockDim.x+threadIdx.x;
  if(t<128*3200){
    int b=t/3200,m=t%3200;
    int node=g_IN1[b*400+(m>>3)];
    g_IN2[t]=adj_all[node*8+(m&7)];
    g_W1n[t]=num_w[node*8+(m&7)];
  }
}
__global__ void k_sess(const int* __restrict__ item,const int* __restrict__ mask,
                       const float* __restrict__ emb){
  int b=blockIdx.x,d=threadIdx.x;
  float acc=0.f,ms=0.f;
  for(int l=0;l<50;l++){
    float mv=(float)mask[b*50+l];
    acc+=emb[(size_t)item[b*50+l]*128+d]*mv; ms+=mv;
  }
  g_SESS[b*128+d]=acc/ms;
}

// ---------------- local agg ----------------
__global__ void __launch_bounds__(256) k_local(const int* __restrict__ inputs,
    const int* __restrict__ adj,const float* __restrict__ emb,
    const float* __restrict__ a_local){
  __shared__ float hs[6400];
  __shared__ float al[512];
  __shared__ float hik[512];
  __shared__ float es[50];
  __shared__ float att[50];
  int b=blockIdx.x,t=threadIdx.x,warp=t>>5,lane=t&31;
  for(int i=t;i<6400;i+=256) hs[i]=emb[(size_t)inputs[b*50+(i>>7)]*128+(i&127)];
  for(int i=t;i<512;i+=256) al[i]=a_local[i];
  __syncthreads();
  for(int ii=0;ii<50;ii++){
    if(t<128){
      float hv=hs[ii*128+t];
      #pragma unroll
      for(int k=0;k<4;k++) hik[k*128+t]=hv*al[k*128+t];
    }
    __syncthreads();
    for(int jj=warp;jj<50;jj+=8){
      int aj=adj[b*2500+ii*50+jj];
      int k=aj>0?aj-1:0;
      const float4* hk=(const float4*)(hik+k*128);
      const float4* hj=(const float4*)(hs+jj*128);
      float4 p=hk[lane],q=hj[lane];
      float v=p.x*q.x+p.y*q.y+p.z*q.z+p.w*q.w;
      for(int o=16;o;o>>=1) v+=__shfl_xor_sync(0xffffffffu,v,o);
      float e=(aj>0)?(v>0.f?v:0.2f*v):-9e15f;
      if(lane==0) es[jj]=e;
    }
    __syncthreads();
    if(warp==0){
      float m1=-3.4e38f;
      for(int j=lane;j<50;j+=32) m1=fmaxf(m1,es[j]);
      for(int o=16;o;o>>=1) m1=fmaxf(m1,__shfl_xor_sync(0xffffffffu,m1,o));
      float ss=0.f;
      for(int j=lane;j<50;j+=32){ float ex=expf(es[j]-m1); att[j]=ex; ss+=ex; }
      for(int o=16;o;o>>=1) ss+=__shfl_xor_sync(0xffffffffu,ss,o);
      float inv=1.f/ss;
      for(int j=lane;j<50;j+=32) att[j]*=inv;
    }
    __syncthreads();
    if(t<128){
      float acc=0.f;
      for(int j=0;j<50;j++) acc+=att[j]*hs[j*128+t];
      g_HL[(size_t)b*6400+ii*128+t]=acc;
    }
    __syncthreads();
  }
}

// ===== attention core (variant C lane tiling): per lane 2 mi x 16 d ========
// Reduction tree reproduces  p += shfl_xor(p,16/8/4/2/1)  over old-lane=d/4
// exactly: stage16 -> shfl_down 4, stage8 -> 2, stage4 -> 1, then local
// (w0+w2)+(w1+w3).
#define ATT_BODY(NV_SRC,NW_SRC,OUT_NG,MTOT)                                    \
  {                                                                            \
    const float4* NV4=(const float4*)nv;                                       \
    int lg=lane>>3, la=lane&7;                                                 \
    int rowA=(lg*2)*8+s, rowB=(lg*2+1)*8+s;                                    \
    int wb=la*4, dbase=la*16;                                                  \
    unsigned long long acc2[2][8];                                             \
    _Pragma("unroll")                                                          \
    for(int p=0;p<8;p++){ acc2[0][p]=0ull; acc2[1][p]=0ull; }                  \
    for(int e4=0;e4<32;e4++){                                                  \
      float4 a0=NV4[rowA*32+e4];                                               \
      float4 a1=NV4[rowB*32+e4];                                               \
      _Pragma("unroll")                                                        \
      for(int j=0;j<4;j++){                                                    \
        float c0=(j==0)?a0.x:(j==1)?a0.y:(j==2)?a0.z:a0.w;                     \
        float c1=(j==0)?a1.x:(j==1)?a1.y:(j==2)?a1.z:a1.w;                     \
        int er=(e4*4+j)*32+wb;                                                 \
        ulonglong2 w0=WT8[er+0];                                               \
        ulonglong2 w1=WT8[er+1];                                               \
        ulonglong2 w2=WT8[er+2];                                               \
        ulonglong2 w3=WT8[er+3];                                               \
        unsigned long long p0=f2pack(c0,c0);                                   \
        unsigned long long p1=f2pack(c1,c1);                                   \
        ffma2(acc2[0][0],p0,w0.x); ffma2(acc2[0][1],p0,w0.y);                  \
        ffma2(acc2[0][2],p0,w1.x); ffma2(acc2[0][3],p0,w1.y);                  \
        ffma2(acc2[0][4],p0,w2.x); ffma2(acc2[0][5],p0,w2.y);                  \
        ffma2(acc2[0][6],p0,w3.x); ffma2(acc2[0][7],p0,w3.y);                  \
        ffma2(acc2[1][0],p1,w0.x); ffma2(acc2[1][1],p1,w0.y);                  \
        ffma2(acc2[1][2],p1,w1.x); ffma2(acc2[1][3],p1,w1.y);                  \
        ffma2(acc2[1][4],p1,w2.x); ffma2(acc2[1][5],p1,w2.y);                  \
        ffma2(acc2[1][6],p1,w3.x); ffma2(acc2[1][7],p1,w3.y);                  \
      }                                                                        \
    }                                                                          \
    _Pragma("unroll")                                                          \
    for(int mm=0;mm<2;mm++){                                                   \
      int mi=lg*2+mm;                                                          \
      float v[16];                                                             \
      _Pragma("unroll")                                                        \
      for(int p=0;p<8;p++) f2unpack(acc2[mm][p],v[2*p],v[2*p+1]);              \
      float nwv=nws[mi*8+s];                                                   \
      _Pragma("unroll")                                                        \
      for(int j=0;j<16;j++){                                                   \
        float vv=v[j]+nwv*w129[dbase+j];                                       \
        v[j]=vv>0.f?vv:0.2f*vv;                                                \
      }                                                                        \
      float part0=v[0]*g2[dbase]+v[1]*g2[dbase+1]+v[2]*g2[dbase+2]+v[3]*g2[dbase+3];   \
      float part1=v[4]*g2[dbase+4]+v[5]*g2[dbase+5]+v[6]*g2[dbase+6]+v[7]*g2[dbase+7]; \
      float part2=v[8]*g2[dbase+8]+v[9]*g2[dbase+9]+v[10]*g2[dbase+10]+v[11]*g2[dbase+11]; \
      float part3=v[12]*g2[dbase+12]+v[13]*g2[dbase+13]+v[14]*g2[dbase+14]+v[15]*g2[dbase+15]; \
      float r0=part0+__shfl_down_sync(0xffffffffu,part0,4);                    \
      float r1=part1+__shfl_down_sync(0xffffffffu,part1,4);                    \
      float r2=part2+__shfl_down_sync(0xffffffffu,part2,4);                    \
      float r3=part3+__shfl_down_sync(0xffffffffu,part3,4);                    \
      float u0=r0+__shfl_down_sync(0xffffffffu,r0,2);                          \
      float u1=r1+__shfl_down_sync(0xffffffffu,r1,2);                          \
      float u2=r2+__shfl_down_sync(0xffffffffu,r2,2);                          \
      float u3=r3+__shfl_down_sync(0xffffffffu,r3,2);                          \
      float q0=u0+__shfl_down_sync(0xffffffffu,u0,1);                          \
      float q1=u1+__shfl_down_sync(0xffffffffu,u1,1);                          \
      float q2=u2+__shfl_down_sync(0xffffffffu,u2,1);                          \
      float q3=u3+__shfl_down_sync(0xffffffffu,u3,1);                          \
      float fin=(q0+q2)+(q1+q3);                                               \
      if(la==0) sc[mi*8+s]=fin;                                                \
    }                                                                          \
    __syncthreads();                                                           \
    if(t<64){                                                                  \
      float vv=sc[t];                                                          \
      float mx=vv;                                                             \
      for(int o=4;o;o>>=1) mx=fmaxf(mx,__shfl_xor_sync(0xffffffffu,mx,o));     \
      exs[t]=expf(vv-mx);                                                      \
    }                                                                          \
    __syncthreads();                                                           \
    if(t==0){                                                                  \
      _Pragma("unroll")                                                        \
      for(int mi=0;mi<8;mi++){                                                 \
        float ss=0.f;                                                          \
        _Pragma("unroll")                                                      \
        for(int i=0;i<8;i++) ss+=exs[mi*8+i];                                  \
        float inv=1.f/ss;                                                      \
        _Pragma("unroll")                                                      \
        for(int i=0;i<8;i++) al[mi*8+i]=exs[mi*8+i]*inv;                       \
      }                                                                        \
    }                                                                          \
    __syncthreads();                                                           \
    {                                                                          \
      int half=t>>7, tt=t&127;                                                 \
      _Pragma("unroll")                                                        \
      for(int q=0;q<4;q++){                                                    \
        int mi=half*4+q;                                                       \
        int m=m0+mi;                                                           \
        if(m<MTOT){                                                            \
          float a2=0.f;                                                        \
          _Pragma("unroll")                                                    \
          for(int i=0;i<8;i++) a2+=al[mi*8+i]*nv[(mi*8+i)*128+tt];             \
          OUT_NG[((size_t)b*MTOT+m)*128+tt]=a2;                                \
        }                                                                      \
      }                                                                        \
    }                                                                          \
    __syncthreads();                                                           \
  }

// ---------------- hop-0 global attention: flattened queue ------------------
__global__ void __launch_bounds__(256) k_att2(int Q,
    const float* __restrict__ emb,const float* __restrict__ gw1h,
    const float* __restrict__ gw2h){
  extern __shared__ float sm[];
  float* wt  = sm;         // 16384 [e][d]
  float* nv  = sm+16384;   // 8192 : 64 rows of 128
  float* w129= sm+24576;   // 128
  float* g2  = sm+24704;   // 128
  float* sc  = sm+24832;   // 64
  float* al  = sm+24896;   // 64
  float* nws = sm+24960;   // 64
  float* exs = sm+25024;   // 64
  int t=threadIdx.x,lane=t&31,s=t>>5;
  if(t<128){ w129[t]=gw1h[16384+t]; g2[t]=gw2h[t]; }
  const ulonglong2* WT8=(const ulonglong2*)wt;
  int g0=blockIdx.x*Q, g1=min(g0+Q,7296);
  int cur_b=-1;
  for(int g=g0;g<g1;g++){
    int b=g/57, c=g-b*57;
    if(b!=cur_b){
      __syncthreads();
      for(int i=t;i<16384;i+=256) wt[i]=g_SESS[b*128+(i>>7)]*gw1h[i];
      cur_b=b;
      __syncthreads();
    }
    int is1=(c>=7);
    int Mtot=is1?400:50;
    int m0=(is1?(c-7):c)*8;
    const int* nidx = is1?g_IN2:g_IN1;
    const float* nwp = is1?g_W1n:g_W0;
    float* outNG = is1?g_NG1:g_NG0;
    #pragma unroll
    for(int mi=0;mi<8;mi++){
      int m=min(m0+mi,Mtot-1);
      size_t base=((size_t)b*Mtot+m)*8+(size_t)s;
      size_t rowid=(size_t)nidx[base];
      ((float4*)nv)[(mi*8+s)*32+lane]=((const float4*)emb)[rowid*32+lane];
    }
    if(t<64){
      int mi=t>>3, ss=t&7;
      int m=min(m0+mi,Mtot-1);
      nws[t]=nwp[((size_t)b*Mtot+m)*8+ss];
    }
    __syncthreads();
    ATT_BODY(emb,nwp,outNG,Mtot)
  }
}

// ---------------- hop-1 attention (src = g_A1 rows) -------------------------
__global__ void __launch_bounds__(256) k_attm2(int Q,
    const float* __restrict__ gw1h,const float* __restrict__ gw2h){
  extern __shared__ float sm[];
  float* wt  = sm;
  float* nv  = sm+16384;
  float* w129= sm+24576;
  float* g2  = sm+24704;
  float* sc  = sm+24832;
  float* al  = sm+24896;
  float* nws = sm+24960;
  float* exs = sm+25024;
  int t=threadIdx.x,lane=t&31,s=t>>5;
  if(t<128){ w129[t]=gw1h[16384+t]; g2[t]=gw2h[t]; }
  const ulonglong2* WT8=(const ulonglong2*)wt;
  int g0=blockIdx.x*Q, g1=min(g0+Q,896);
  int cur_b=-1;
  for(int g=g0;g<g1;g++){
    int b=g/7, c=g-b*7;
    if(b!=cur_b){
      __syncthreads();
      for(int i=t;i<16384;i+=256) wt[i]=g_SESS[b*128+(i>>7)]*gw1h[i];
      cur_b=b;
      __syncthreads();
    }
    const int Mtot=50;
    int m0=c*8;
    #pragma unroll
    for(int mi=0;mi<8;mi++){
      int m=min(m0+mi,Mtot-1);
      size_t base=((size_t)b*Mtot+m)*8+(size_t)s;
      ((float4*)nv)[(mi*8+s)*32+lane]=((const float4*)g_A1)[base*32+lane];
    }
    if(t<64){
      int mi=t>>3, ss=t&7;
      int m=min(m0+mi,Mtot-1);
      nws[t]=g_W0[((size_t)b*Mtot+m)*8+ss];
    }
    __syncthreads();
    ATT_BODY(g_A1,g_W0,g_NG0,Mtot)
  }
}

// -------- linear (concat 256 -> 128), persistent, FFMA2, 512 thr, 64 rows --
__global__ void __launch_bounds__(512) k_lin(int nrows,int cfg,
    const int* __restrict__ idxtab,const float* __restrict__ extA,
    const float* __restrict__ extB,const float* __restrict__ w){
  extern __shared__ float sm[];
  float* ws=sm;          // 32768 [e][d]
  float* inT=sm+32768;   // 16384 [e][64]
  int t=threadIdx.x;
  for(int i=t;i<32768;i+=512) ws[i]=w[i];
  int ngroups=(nrows+63)>>6;
  float* outp=(cfg==0)?g_A0:(cfg==1)?g_A1:(cfg==2)?g_HG:g_NH;
  float pf[32];
  int grp=blockIdx.x;

#define LIN_LOAD_PF(GRP) do{ \
    int row0p=(GRP)*64; \
    _Pragma("unroll") \
    for(int k=0;k<32;k++){ \
      int i=t+k*512; int r=i&63,e=i>>6,row=row0p+r; \
      float v=0.f; \
      if(row<nrows){ \
        if(e<128){ \
          if(cfg==0)      v=extA[(size_t)idxtab[row]*128+e]; \
          else if(cfg==1) v=extA[(size_t)g_IN1[row]*128+e]; \
          else if(cfg==2) v=g_A0[(size_t)row*128+e]; \
          else            v=extA[(size_t)(row%50)*128+e]; \
        }else{ \
          int e2=e-128; \
          if(cfg==0)      v=g_NG0[(size_t)row*128+e2]; \
          else if(cfg==1) v=g_NG1[(size_t)row*128+e2]; \
          else if(cfg==2) v=g_NG0[(size_t)row*128+e2]; \
          else            v=extB[(size_t)row*128+e2]; \
        } \
      } \
      pf[k]=v; \
    } \
  }while(0)

  if(grp<ngroups) LIN_LOAD_PF(grp);
  for(;grp<ngroups;grp+=gridDim.x){
    __syncthreads();
    #pragma unroll
    for(int k=0;k<32;k++) inT[t+k*512]=pf[k];
    __syncthreads();
    int nxt=grp+gridDim.x;
    if(nxt<ngroups) LIN_LOAD_PF(nxt);
    int row0=grp*64;
    int d=t&127,rh=t>>7;   // rh in 0..3, rows rh*16..rh*16+15
    unsigned long long acc2[8];
    #pragma unroll
    for(int q=0;q<8;q++) acc2[q]=0ull;
    const ulonglong2* I8=(const ulonglong2*)inT;
    for(int e=0;e<256;e++){
      float wv=ws[e*128+d];
      unsigned long long wv2=f2pack(wv,wv);
      ulonglong2 u0=I8[e*16+rh*4+0];
      ulonglong2 u1=I8[e*16+rh*4+1];
      ulonglong2 u2=I8[e*16+rh*4+2];
      ulonglong2 u3=I8[e*16+rh*4+3];
      ffma2(acc2[0],wv2,u0.x); ffma2(acc2[1],wv2,u0.y);
      ffma2(acc2[2],wv2,u1.x); ffma2(acc2[3],wv2,u1.y);
      ffma2(acc2[4],wv2,u2.x); ffma2(acc2[5],wv2,u2.y);
      ffma2(acc2[6],wv2,u3.x); ffma2(acc2[7],wv2,u3.y);
    }
    #pragma unroll
    for(int q=0;q<8;q++){
      float lo,hi;
      f2unpack(acc2[q],lo,hi);
      int rlo=row0+rh*16+q*2;
      if(rlo<nrows){
        float v=(cfg==3)?tanhf(lo):fmaxf(lo,0.f);
        outp[(size_t)rlo*128+d]=v;
      }
      if(rlo+1<nrows){
        float v=(cfg==3)?tanhf(hi):fmaxf(hi,0.f);
        outp[(size_t)(rlo+1)*128+d]=v;
      }
    }
  }
#undef LIN_LOAD_PF
}

// ---------------- mix / ssl ----------------
__global__ void k_mix(float* __restrict__ out){
  int i=blockIdx.x*blockDim.x+threadIdx.x;
  if(i<819200) out[i]=g_HL[i]+g_HG[i];
}
__global__ void k_ssl(){
  __shared__ float red[128];
  int b=blockIdx.x,t=threadIdx.x;
  int pb=g_PR[b];
  float pos=0.f,neg=0.f;
  for(int l=0;l<50;l++){
    float hl=g_HL[(size_t)b*6400+l*128+t];
    float hg=g_HG[(size_t)b*6400+l*128+t];
    pos+=hl*hg;
    neg+=hg*g_HL[(size_t)pb*6400+g_PC[l]*128+t];
  }
  float sp=1.f/(1.f+expf(-pos)),sn=1.f/(1.f+expf(-neg));
  float term=-logf(1e-8f+sp)-logf(1e-8f+1.f-sn);
  red[t]=term; __syncthreads();
  for(int o=64;o;o>>=1){ if(t<o) red[t]+=red[t+o]; __syncthreads(); }
  if(t==0) g_LP[b]=red[0];
}
__global__ void k_fin(float* __restrict__ out){
  __shared__ float r[128];
  int t=threadIdx.x;
  r[t]=g_LP[t]; __syncthreads();
  for(int o=64;o;o>>=1){ if(t<o) r[t]+=r[t+o]; __syncthreads(); }
  if(t==0) out[819200]=0.005f*r[0];
}

// ---------------- glu/select ----------------
__global__ void __launch_bounds__(256) k_glu(const float* __restrict__ hidden,
    const int* __restrict__ mask,const float* __restrict__ glu1w,
    const float* __restrict__ glu1b,const float* __restrict__ glu2w,
    const float* __restrict__ w2){
  extern __shared__ float sm[];
  float* g1t=sm;        // 16384 [e][d]
  float* hS =sm+16384;  // 6400
  float* nhS=sm+22784;  // 6400
  float* hs =sm+29184;  // 128
  float* t2 =sm+29312;  // 128
  float* bet=sm+29440;  // 64
  float* w2s=sm+29504;  // 128
  float* b1s=sm+29632;  // 128
  int b=blockIdx.x,t=threadIdx.x,warp=t>>5,lane=t&31;
  for(int i=t;i<16384;i+=256){ int e=i>>7,d=i&127; g1t[i]=glu1w[d*128+e]; }
  for(int i=t;i<6400;i+=256){ hS[i]=hidden[(size_t)b*6400+i]; nhS[i]=g_NH[(size_t)b*6400+i]; }
  if(t<128){ w2s[t]=w2[t]; b1s[t]=glu1b[t]; }
  __syncthreads();
  if(t<128){
    float a=0.f,ms=0.f;
    for(int l=0;l<50;l++){ float mv=(float)mask[b*50+l]; a+=hS[l*128+t]*mv; ms+=mv; }
    hs[t]=a/ms;
  }
  __syncthreads();
  if(t<128){
    float a=0.f;
    for(int e=0;e<128;e++) a+=hs[e]*glu2w[t*128+e];
    t2[t]=a;
  }
  __syncthreads();
  const float4* G14=(const float4*)g1t;
  for(int lb=0;lb<56;lb+=8){
    int l=lb+warp;
    if(l<50){
      const float4* N4=(const float4*)(nhS+l*128);
      float a0=0,a1=0,a2=0,a3=0;
      #pragma unroll 4
      for(int e4=0;e4<32;e4++){
        float4 a=N4[e4];
        float4 w=G14[(e4*4+0)*32+lane];
        a0+=a.x*w.x; a1+=a.x*w.y; a2+=a.x*w.z; a3+=a.x*w.w;
        w=G14[(e4*4+1)*32+lane];
        a0+=a.y*w.x; a1+=a.y*w.y; a2+=a.y*w.z; a3+=a.y*w.w;
        w=G14[(e4*4+2)*32+lane];
        a0+=a.z*w.x; a1+=a.z*w.y; a2+=a.z*w.z; a3+=a.z*w.w;
        w=G14[(e4*4+3)*32+lane];
        a0+=a.w*w.x; a1+=a.w*w.y; a2+=a.w*w.z; a3+=a.w*w.w;
      }
      int d0=lane*4;
      a0=1.f/(1.f+expf(-(a0+b1s[d0]+t2[d0])));
      a1=1.f/(1.f+expf(-(a1+b1s[d0+1]+t2[d0+1])));
      a2=1.f/(1.f+expf(-(a2+b1s[d0+2]+t2[d0+2])));
      a3=1.f/(1.f+expf(-(a3+b1s[d0+3]+t2[d0+3])));
      float p=a0*w2s[d0]+a1*w2s[d0+1]+a2*w2s[d0+2]+a3*w2s[d0+3];
      for(int o=16;o;o>>=1) p+=__shfl_xor_sync(0xffffffffu,p,o);
      if(lane==0) bet[l]=p*(float)mask[b*50+l];
    }
  }
  __syncthreads();
  if(t<128){
    float a=0.f;
    for(int l=0;l<50;l++) a+=bet[l]*hS[l*128+t];
    g_SEL[b*128+t]=a;
  }
}

// ---------------- neighbor top-k ----------------
__global__ void __launch_bounds__(128) k_nbr(){
  extern __shared__ float sm[];
  float* sel=sm;  // 16384
  __shared__ float nrm[128];
  __shared__ float ev[128];
  __shared__ float tv[9];
  __shared__ int   ti[9];
  __shared__ float red[4];
  int b=blockIdx.x,t=threadIdx.x;
  for(int i=t;i<16384;i+=128) sel[i]=g_SEL[i];
  __syncthreads();
  { float a=0.f;
    for(int d=0;d<128;d++){ float v=sel[t*128+d]; a+=v*v; }
    nrm[t]=sqrtf(a+128e-6f); }
  __syncthreads();
  float dot=0.f;
  for(int d=0;d<128;d++) dot+=sel[b*128+d]*sel[t*128+d];
  float e=dot/(nrm[b]*nrm[t]);
  float mx=e;
  for(int o=16;o;o>>=1) mx=fmaxf(mx,__shfl_xor_sync(0xffffffffu,mx,o));
  if((t&31)==0) red[t>>5]=mx;
  __syncthreads();
  mx=fmaxf(fmaxf(red[0],red[1]),fmaxf(red[2],red[3]));
  float ex=expf(e-mx);
  float ss=ex;
  for(int o=16;o;o>>=1) ss+=__shfl_xor_sync(0xffffffffu,ss,o);
  __syncthreads();
  if((t&31)==0) red[t>>5]=ss;
  __syncthreads();
  ss=red[0]+red[1]+red[2]+red[3];
  ev[t]=ex/ss;
  __syncthreads();
  if(t==0){
    for(int k=0;k<9;k++){
      float bv=-1.f; int bi=0;
      for(int j=0;j<128;j++) if(ev[j]>bv){ bv=ev[j]; bi=j; }
      tv[k]=bv; ti[k]=bi; ev[bi]=-2.f;
    }
    float m2=tv[0],s2=0.f;
    for(int k=0;k<9;k++){ tv[k]=expf(tv[k]-m2); s2+=tv[k]; }
    float inv=1.f/s2;
    for(int k=0;k<9;k++) tv[k]*=inv;
  }
  __syncthreads();
  float nb=0.f;
  #pragma unroll
  for(int k=0;k<9;k++) nb+=tv[k]*sel[ti[k]*128+t];
  g_SEL2T[t*128+b]=sel[b*128+t]+nb;
}

// ---------------- scores GEMM (FFMA2, 512 threads) ----------------
__global__ void __launch_bounds__(512) k_scores(const float* __restrict__ emb,
                                                float* __restrict__ outp){
  extern __shared__ float sm[];
  float* selT=sm;        // 16384 [e][b]
  float* embT=sm+16384;  // 128*129 [e][j] stride 129
  int t=threadIdx.x;
  int j0=blockIdx.x*128;
  for(int i=t;i<16384;i+=512) selT[i]=g_SEL2T[i];
  for(int i=t;i<16384;i+=512){
    int j=i>>7,e=i&127;
    int node=1+j0+j;
    embT[e*129+j]=(node<100000)?emb[(size_t)node*128+e]:0.f;
  }
  __syncthreads();
  int j=t&127,bh=t>>7;   // bh in 0..3, b range bh*32..bh*32+31
  unsigned long long acc2[16];
  #pragma unroll
  for(int q=0;q<16;q++) acc2[q]=0ull;
  const ulonglong2* S8=(const ulonglong2*)selT;
  for(int e=0;e<128;e++){
    float evv=embT[e*129+j];
    unsigned long long ev2=f2pack(evv,evv);
    const ulonglong2* s=&S8[e*32+bh*8];
    #pragma unroll
    for(int q=0;q<8;q++){
      ulonglong2 u=s[q];
      ffma2(acc2[q*2+0],ev2,u.x);
      ffma2(acc2[q*2+1],ev2,u.y);
    }
  }
  if(j0+j<99999){
    #pragma unroll
    for(int q=0;q<8;q++){
      float l0,h0,l1,h1;
      f2unpack(acc2[q*2+0],l0,h0);
      f2unpack(acc2[q*2+1],l1,h1);
      int b=bh*32+q*4;
      outp[(size_t)b*99999+j0+j]=l0;
      outp[(size_t)(b+1)*99999+j0+j]=h0;
      outp[(size_t)(b+2)*99999+j0+j]=l1;
      outp[(size_t)(b+3)*99999+j0+j]=h1;
    }
  }
}

// ---------------- launch ----------------
extern "C" void kernel_launch(void* const* d_in,const int* in_sizes,int n_in,
                              void* d_out,int out_size){
  const int*   inputs =(const int*)d_in[0];
  const int*   adj    =(const int*)d_in[1];
  const int*   mask   =(const int*)d_in[2];
  const int*   item   =(const int*)d_in[3];
  const int*   adj_all=(const int*)d_in[5];
  const float* num_w  =(const float*)d_in[6];
  const float* emb    =(const float*)d_in[7];
  const float* pos    =(const float*)d_in[8];
  const float* a_local=(const float*)d_in[9];
  const float* gw1    =(const float*)d_in[10];
  const float* gw2    =(const float*)d_in[11];
  const float* gw3    =(const float*)d_in[12];
  const float* w1     =(const float*)d_in[13];
  const float* w2     =(const float*)d_in[14];
  const float* g1w    =(const float*)d_in[15];
  const float* g1b    =(const float*)d_in[16];
  const float* g2w    =(const float*)d_in[17];
  float* out=(float*)d_out;

  const size_t SM_ATT=25088u*4u;   // 100,352 B -> 2 blocks/SM
  const size_t SM_LIN=49152u*4u;   // 196,608 B -> 1 block/SM, 16 warps
  const size_t SM_GLU=29760u*4u;
  const size_t SM_SC =32896u*4u;
  const size_t SM_NBR=16384u*4u;
  cudaFuncSetAttribute(k_att2,  cudaFuncAttributeMaxDynamicSharedMemorySize,(int)SM_ATT);
  cudaFuncSetAttribute(k_attm2, cudaFuncAttributeMaxDynamicSharedMemorySize,(int)SM_ATT);
  cudaFuncSetAttribute(k_lin,   cudaFuncAttributeMaxDynamicSharedMemorySize,(int)SM_LIN);
  cudaFuncSetAttribute(k_glu,   cudaFuncAttributeMaxDynamicSharedMemorySize,(int)SM_GLU);
  cudaFuncSetAttribute(k_scores,cudaFuncAttributeMaxDynamicSharedMemorySize,(int)SM_SC);
  cudaFuncSetAttribute(k_nbr,   cudaFuncAttributeMaxDynamicSharedMemorySize,(int)SM_NBR);

  k_prep1<<<200,256>>>(inputs,adj_all,num_w);
  k_prep2<<<1600,256>>>(adj_all,num_w);
  k_sess<<<128,128>>>(item,mask,emb);
  // hop 0: flattened mode0+mode1 attention (7296 chunks over 296 resident blocks)
  k_att2<<<296,256,SM_ATT>>>(25,emb,gw1,gw2);                        // -> g_NG0, g_NG1
  k_perm<<<1,128>>>();
  k_local<<<128,256>>>(inputs,adj,emb,a_local);
  k_lin<<<100,512,SM_LIN>>>(6400,0,inputs,emb,0,gw3);                // -> g_A0
  k_lin<<<148,512,SM_LIN>>>(51200,1,0,emb,0,gw3);                    // -> g_A1
  // hop 1 (896 chunks over 224 blocks = 1 wave)
  k_attm2<<<224,256,SM_ATT>>>(4,gw1+129*128,gw2+128);                // -> g_NG0
  k_lin<<<100,512,SM_LIN>>>(6400,2,0,0,0,gw3+256*128);               // -> g_HG
  // outputs
  k_mix<<<3200,256>>>(out);
  k_ssl<<<128,128>>>();
  k_fin<<<1,128>>>(out);
  // scores head
  k_lin<<<100,512,SM_LIN>>>(6400,3,0,pos,out,w1);                    // -> g_NH
  k_glu<<<128,256,SM_GLU>>>(out,mask,g1w,g1b,g2w,w2);
  k_nbr<<<128,128,SM_NBR>>>();
  k_scores<<<782,512,SM_SC>>>(emb,out+819201);
}

// round 12
// speedup vs baseline: 2.2554x; 2.2554x over previous
#include <cuda_runtime.h>
#include <math.h>

// ---------------- f32x2 packed-FMA helpers (bitwise = 2x IEEE fp32 FMA) ----
__device__ __forceinline__ unsigned long long f2pack(float x,float y){
  unsigned long long r;
  asm("mov.b64 %0,{%1,%2};":"=l"(r):"r"(__float_as_uint(x)),"r"(__float_as_uint(y)));
  return r;
}
__device__ __forceinline__ void f2unpack(unsigned long long v,float&x,float&y){
  unsigned ux,uy;
  asm("mov.b64 {%0,%1},%2;":"=r"(ux),"=r"(uy):"l"(v));
  x=__uint_as_float(ux); y=__uint_as_float(uy);
}
__device__ __forceinline__ void ffma2(unsigned long long&d,unsigned long long a,unsigned long long b){
  asm("fma.rn.f32x2 %0,%1,%2,%0;":"+l"(d):"l"(a),"l"(b));
}

// ---------------- scratch ----------------
__device__ float g_SESS[128*128];
__device__ int   g_IN1[128*400];
__device__ float g_W0 [128*400];
__device__ int   g_IN2[128*3200];
__device__ float g_W1n[128*3200];
__device__ float g_NG0[128*50*128];
__device__ float g_NG1[128*400*128];
__device__ float g_A0 [128*50*128];
__device__ float g_A1 [128*400*128];
__device__ float g_HL [128*50*128];
__device__ float g_HG [128*50*128];
__device__ float g_NH [128*50*128];
__device__ float g_SEL[128*128];
__device__ float g_SEL2T[128*128];
__device__ float g_LP[128];
__device__ int   g_PR[128];
__device__ int   g_PC[64];

// ---------------- threefry ----------------
__device__ __forceinline__ void tf(unsigned k0,unsigned k1,unsigned x0,unsigned x1,
                                   unsigned&o0,unsigned&o1){
  unsigned ks2=k0^k1^0x1BD11BDAu;
  x0+=k0; x1+=k1;
#define RND(r) {x0+=x1; x1=(x1<<(r))|(x1>>(32-(r))); x1^=x0;}
  RND(13)RND(15)RND(26)RND(6)   x0+=k1;  x1+=ks2+1u;
  RND(17)RND(29)RND(16)RND(24)  x0+=ks2; x1+=k0+2u;
  RND(13)RND(15)RND(26)RND(6)   x0+=k0;  x1+=k1+3u;
  RND(17)RND(29)RND(16)RND(24)  x0+=k1;  x1+=ks2+4u;
  RND(13)RND(15)RND(26)RND(6)   x0+=ks2; x1+=k0+5u;
#undef RND
  o0=x0; o1=x1;
}

__global__ void k_perm(){
  __shared__ unsigned keys[4];
  __shared__ unsigned br[128];
  __shared__ unsigned bc[64];
  int t=threadIdx.x;
  if(t==0){
    unsigned u0,u1,v0,v1,p0,p1,q0,q1;
    tf(0u,42u,0u,2u,u0,u1); tf(0u,42u,1u,3u,v0,v1);
    unsigned kr0=u0,kr1=v0,kc0=u1,kc1=v1;
    tf(kr0,kr1,0u,2u,p0,p1); tf(kr0,kr1,1u,3u,q0,q1);
    keys[0]=p1; keys[1]=q1;
    tf(kc0,kc1,0u,2u,p0,p1); tf(kc0,kc1,1u,3u,q0,q1);
    keys[2]=p1; keys[3]=q1;
  }
  __syncthreads();
  { int j=t&63; unsigned w0,w1;
    tf(keys[0],keys[1],(unsigned)j,(unsigned)(j+64),w0,w1);
    br[t]=(t<64)?w0:w1; }
  if(t<50){ int j=(t<25)?t:t-25; unsigned w0,w1;
    tf(keys[2],keys[3],(unsigned)j,(unsigned)(j+25),w0,w1);
    bc[t]=(t<25)?w0:w1; }
  __syncthreads();
  { unsigned mine=br[t]; int r=0;
    for(int j=0;j<128;j++){ unsigned bj=br[j]; r+=(bj<mine)||(bj==mine&&j<t); }
    g_PR[r]=t; }
  if(t<50){ unsigned mine=bc[t]; int r=0;
    for(int j=0;j<50;j++){ unsigned bj=bc[j]; r+=(bj<mine)||(bj==mine&&j<t); }
    g_PC[r]=t; }
}

// ---------------- prep ----------------
__global__ void k_prep1(const int* __restrict__ inputs,const int* __restrict__ adj_all,
                        const float* __restrict__ num_w){
  int t=blockIdx.x*blockDim.x+threadIdx.x;
  if(t<128*400){
    int b=t/400,m=t%400;
    int node=inputs[b*50+(m>>3)];
    g_IN1[t]=adj_all[node*8+(m&7)];
    g_W0[t]=num_w[node*8+(m&7)];
  }
}
__global__ void k_prep2(const int* __restrict__ adj_all,const float* __restrict__ num_w){
  int t=blockIdx.x*blockDim.x+threadIdx.x;
  if(t<128*3200){
    int b=t/3200,m=t%3200;
    int node=g_IN1[b*400+(m>>3)];
    g_IN2[t]=adj_all[node*8+(m&7)];
    g_W1n[t]=num_w[node*8+(m&7)];
  }
}
__global__ void k_sess(const int* __restrict__ item,const int* __restrict__ mask,
                       const float* __restrict__ emb){
  int b=blockIdx.x,d=threadIdx.x;
  float acc=0.f,ms=0.f;
  for(int l=0;l<50;l++){
    float mv=(float)mask[b*50+l];
    acc+=emb[(size_t)item[b*50+l]*128+d]*mv; ms+=mv;
  }
  g_SESS[b*128+d]=acc/ms;
}

// ---------------- local agg ----------------
__global__ void __launch_bounds__(256) k_local(const int* __restrict__ inputs,
    const int* __restrict__ adj,const float* __restrict__ emb,
    const float* __restrict__ a_local){
  __shared__ float hs[6400];
  __shared__ float al[512];
  __shared__ float hik[512];
  __shared__ float es[50];
  __shared__ float att[50];
  int b=blockIdx.x,t=threadIdx.x,warp=t>>5,lane=t&31;
  for(int i=t;i<6400;i+=256) hs[i]=emb[(size_t)inputs[b*50+(i>>7)]*128+(i&127)];
  for(int i=t;i<512;i+=256) al[i]=a_local[i];
  __syncthreads();
  for(int ii=0;ii<50;ii++){
    if(t<128){
      float hv=hs[ii*128+t];
      #pragma unroll
      for(int k=0;k<4;k++) hik[k*128+t]=hv*al[k*128+t];
    }
    __syncthreads();
    for(int jj=warp;jj<50;jj+=8){
      int aj=adj[b*2500+ii*50+jj];
      int k=aj>0?aj-1:0;
      const float4* hk=(const float4*)(hik+k*128);
      const float4* hj=(const float4*)(hs+jj*128);
      float4 p=hk[lane],q=hj[lane];
      float v=p.x*q.x+p.y*q.y+p.z*q.z+p.w*q.w;
      for(int o=16;o;o>>=1) v+=__shfl_xor_sync(0xffffffffu,v,o);
      float e=(aj>0)?(v>0.f?v:0.2f*v):-9e15f;
      if(lane==0) es[jj]=e;
    }
    __syncthreads();
    if(warp==0){
      float m1=-3.4e38f;
      for(int j=lane;j<50;j+=32) m1=fmaxf(m1,es[j]);
      for(int o=16;o;o>>=1) m1=fmaxf(m1,__shfl_xor_sync(0xffffffffu,m1,o));
      float ss=0.f;
      for(int j=lane;j<50;j+=32){ float ex=expf(es[j]-m1); att[j]=ex; ss+=ex; }
      for(int o=16;o;o>>=1) ss+=__shfl_xor_sync(0xffffffffu,ss,o);
      float inv=1.f/ss;
      for(int j=lane;j<50;j+=32) att[j]*=inv;
    }
    __syncthreads();
    if(t<128){
      float acc=0.f;
      for(int j=0;j<50;j++) acc+=att[j]*hs[j*128+t];
      g_HL[(size_t)b*6400+ii*128+t]=acc;
    }
    __syncthreads();
  }
}

// ---------------- hop-0 global attention: flattened queue, 8-m, FFMA2,
// register-prefetch double buffering (R9 arithmetic, bitwise identical) -----
__global__ void __launch_bounds__(256) k_att2(int Q,
    const float* __restrict__ emb,const float* __restrict__ gw1h,
    const float* __restrict__ gw2h){
  extern __shared__ float sm[];
  float* wt  = sm;         // 16384 [e][d]
  float* nv  = sm+16384;   // 8192 : 64 rows of 128
  float* w129= sm+24576;   // 128
  float* g2  = sm+24704;   // 128
  float* sc  = sm+24832;   // 64
  float* al  = sm+24896;   // 64
  float* nws = sm+24960;   // 64
  float* exs = sm+25024;   // 64
  int t=threadIdx.x,lane=t&31,s=t>>5;
  if(t<128){ w129[t]=gw1h[16384+t]; g2[t]=gw2h[t]; }
  const ulonglong2* WT8=(const ulonglong2*)wt;
  int g0=blockIdx.x*Q, g1=min(g0+Q,7296);
  int cur_b=-1;
  float4 pfv[8];
  float pfw=0.f;
#define ATT2_PRE(G) do{ \
    int bb=(G)/57, cc=(G)-bb*57; \
    int is1p=(cc>=7); \
    int Mt=is1p?400:50; \
    int mm0=(is1p?(cc-7):cc)*8; \
    const int* ni=is1p?g_IN2:g_IN1; \
    const float* nwq=is1p?g_W1n:g_W0; \
    _Pragma("unroll") \
    for(int mi=0;mi<8;mi++){ \
      int m=min(mm0+mi,Mt-1); \
      size_t base=((size_t)bb*Mt+m)*8+(size_t)s; \
      pfv[mi]=((const float4*)emb)[(size_t)ni[base]*32+lane]; \
    } \
    if(t<64){ \
      int mi=t>>3, ssq=t&7; \
      int m=min(mm0+mi,Mt-1); \
      pfw=nwq[((size_t)bb*Mt+m)*8+ssq]; \
    } \
  }while(0)
  if(g0<g1) ATT2_PRE(g0);
  for(int g=g0;g<g1;g++){
    int b=g/57, c=g-b*57;
    if(b!=cur_b){
      for(int i=t;i<16384;i+=256) wt[i]=g_SESS[b*128+(i>>7)]*gw1h[i];
      cur_b=b;
    }
    int is1=(c>=7);
    int Mtot=is1?400:50;
    int m0=(is1?(c-7):c)*8;
    float* outNG = is1?g_NG1:g_NG0;
    #pragma unroll
    for(int mi=0;mi<8;mi++)
      ((float4*)nv)[(mi*8+s)*32+lane]=pfv[mi];
    if(t<64) nws[t]=pfw;
    __syncthreads();
    if(g+1<g1) ATT2_PRE(g+1);
    const float4* NV4=(const float4*)nv;
    unsigned long long acc2[8][2];
    #pragma unroll
    for(int mi=0;mi<8;mi++){ acc2[mi][0]=0ull; acc2[mi][1]=0ull; }
    for(int e4=0;e4<32;e4++){
      ulonglong2 w0 =WT8[(e4*4+0)*32+lane];
      ulonglong2 w1v=WT8[(e4*4+1)*32+lane];
      ulonglong2 w2v=WT8[(e4*4+2)*32+lane];
      ulonglong2 w3v=WT8[(e4*4+3)*32+lane];
      #pragma unroll
      for(int mi=0;mi<8;mi++){
        float4 a=NV4[(mi*8+s)*32+e4];
        unsigned long long ax=f2pack(a.x,a.x);
        unsigned long long ay=f2pack(a.y,a.y);
        unsigned long long az=f2pack(a.z,a.z);
        unsigned long long aw=f2pack(a.w,a.w);
        ffma2(acc2[mi][0],ax,w0.x);  ffma2(acc2[mi][1],ax,w0.y);
        ffma2(acc2[mi][0],ay,w1v.x); ffma2(acc2[mi][1],ay,w1v.y);
        ffma2(acc2[mi][0],az,w2v.x); ffma2(acc2[mi][1],az,w2v.y);
        ffma2(acc2[mi][0],aw,w3v.x); ffma2(acc2[mi][1],aw,w3v.y);
      }
    }
    int d0=lane*4;
    #pragma unroll
    for(int mi=0;mi<8;mi++){
      float a0,a1,a2,a3;
      f2unpack(acc2[mi][0],a0,a1);
      f2unpack(acc2[mi][1],a2,a3);
      float nwv=nws[mi*8+s];
      float v0=a0+nwv*w129[d0];
      float v1=a1+nwv*w129[d0+1];
      float v2=a2+nwv*w129[d0+2];
      float v3=a3+nwv*w129[d0+3];
      v0=v0>0.f?v0:0.2f*v0; v1=v1>0.f?v1:0.2f*v1;
      v2=v2>0.f?v2:0.2f*v2; v3=v3>0.f?v3:0.2f*v3;
      float p=v0*g2[d0]+v1*g2[d0+1]+v2*g2[d0+2]+v3*g2[d0+3];
      for(int o=16;o;o>>=1) p+=__shfl_xor_sync(0xffffffffu,p,o);
      if(lane==0) sc[mi*8+s]=p;
    }
    __syncthreads();
    if(t<64){
      float v=sc[t];
      float mx=v;
      for(int o=4;o;o>>=1) mx=fmaxf(mx,__shfl_xor_sync(0xffffffffu,mx,o));
      exs[t]=expf(v-mx);
    }
    __syncthreads();
    if(t==0){
      #pragma unroll
      for(int mi=0;mi<8;mi++){
        float ss=0.f;
        #pragma unroll
        for(int i=0;i<8;i++) ss+=exs[mi*8+i];
        float inv=1.f/ss;
        #pragma unroll
        for(int i=0;i<8;i++) al[mi*8+i]=exs[mi*8+i]*inv;
      }
    }
    __syncthreads();
    {
      int half=t>>7, tt=t&127;
      #pragma unroll
      for(int q=0;q<4;q++){
        int mi=half*4+q;
        int m=m0+mi;
        if(m<Mtot){
          float a2=0.f;
          #pragma unroll
          for(int i=0;i<8;i++) a2+=al[mi*8+i]*nv[(mi*8+i)*128+tt];
          outNG[((size_t)b*Mtot+m)*128+tt]=a2;
        }
      }
    }
    __syncthreads();
  }
#undef ATT2_PRE
}

// ---------------- hop-1 attention (src = g_A1 rows), 8-m, FFMA2, prefetch --
__global__ void __launch_bounds__(256) k_attm2(int Q,
    const float* __restrict__ gw1h,const float* __restrict__ gw2h){
  extern __shared__ float sm[];
  float* wt  = sm;
  float* nv  = sm+16384;
  float* w129= sm+24576;
  float* g2  = sm+24704;
  float* sc  = sm+24832;
  float* al  = sm+24896;
  float* nws = sm+24960;
  float* exs = sm+25024;
  int t=threadIdx.x,lane=t&31,s=t>>5;
  if(t<128){ w129[t]=gw1h[16384+t]; g2[t]=gw2h[t]; }
  const ulonglong2* WT8=(const ulonglong2*)wt;
  int g0=blockIdx.x*Q, g1=min(g0+Q,896);
  int cur_b=-1;
  float4 pfv[8];
  float pfw=0.f;
#define ATTM_PRE(G) do{ \
    int bb=(G)/7, cc=(G)-bb*7; \
    int mm0=cc*8; \
    _Pragma("unroll") \
    for(int mi=0;mi<8;mi++){ \
      int m=min(mm0+mi,49); \
      size_t base=((size_t)bb*50+m)*8+(size_t)s; \
      pfv[mi]=((const float4*)g_A1)[base*32+lane]; \
    } \
    if(t<64){ \
      int mi=t>>3, ssq=t&7; \
      int m=min(mm0+mi,49); \
      pfw=g_W0[((size_t)bb*50+m)*8+ssq]; \
    } \
  }while(0)
  if(g0<g1) ATTM_PRE(g0);
  for(int g=g0;g<g1;g++){
    int b=g/7, c=g-b*7;
    if(b!=cur_b){
      for(int i=t;i<16384;i+=256) wt[i]=g_SESS[b*128+(i>>7)]*gw1h[i];
      cur_b=b;
    }
    const int Mtot=50;
    int m0=c*8;
    #pragma unroll
    for(int mi=0;mi<8;mi++)
      ((float4*)nv)[(mi*8+s)*32+lane]=pfv[mi];
    if(t<64) nws[t]=pfw;
    __syncthreads();
    if(g+1<g1) ATTM_PRE(g+1);
    const float4* NV4=(const float4*)nv;
    unsigned long long acc2[8][2];
    #pragma unroll
    for(int mi=0;mi<8;mi++){ acc2[mi][0]=0ull; acc2[mi][1]=0ull; }
    for(int e4=0;e4<32;e4++){
      ulonglong2 w0 =WT8[(e4*4+0)*32+lane];
      ulonglong2 w1v=WT8[(e4*4+1)*32+lane];
      ulonglong2 w2v=WT8[(e4*4+2)*32+lane];
      ulonglong2 w3v=WT8[(e4*4+3)*32+lane];
      #pragma unroll
      for(int mi=0;mi<8;mi++){
        float4 a=NV4[(mi*8+s)*32+e4];
        unsigned long long ax=f2pack(a.x,a.x);
        unsigned long long ay=f2pack(a.y,a.y);
        unsigned long long az=f2pack(a.z,a.z);
        unsigned long long aw=f2pack(a.w,a.w);
        ffma2(acc2[mi][0],ax,w0.x);  ffma2(acc2[mi][1],ax,w0.y);
        ffma2(acc2[mi][0],ay,w1v.x); ffma2(acc2[mi][1],ay,w1v.y);
        ffma2(acc2[mi][0],az,w2v.x); ffma2(acc2[mi][1],az,w2v.y);
        ffma2(acc2[mi][0],aw,w3v.x); ffma2(acc2[mi][1],aw,w3v.y);
      }
    }
    int d0=lane*4;
    #pragma unroll
    for(int mi=0;mi<8;mi++){
      float a0,a1,a2,a3;
      f2unpack(acc2[mi][0],a0,a1);
      f2unpack(acc2[mi][1],a2,a3);
      float nwv=nws[mi*8+s];
      float v0=a0+nwv*w129[d0];
      float v1=a1+nwv*w129[d0+1];
      float v2=a2+nwv*w129[d0+2];
      float v3=a3+nwv*w129[d0+3];
      v0=v0>0.f?v0:0.2f*v0; v1=v1>0.f?v1:0.2f*v1;
      v2=v2>0.f?v2:0.2f*v2; v3=v3>0.f?v3:0.2f*v3;
      float p=v0*g2[d0]+v1*g2[d0+1]+v2*g2[d0+2]+v3*g2[d0+3];
      for(int o=16;o;o>>=1) p+=__shfl_xor_sync(0xffffffffu,p,o);
      if(lane==0) sc[mi*8+s]=p;
    }
    __syncthreads();
    if(t<64){
      float v=sc[t];
      float mx=v;
      for(int o=4;o;o>>=1) mx=fmaxf(mx,__shfl_xor_sync(0xffffffffu,mx,o));
      exs[t]=expf(v-mx);
    }
    __syncthreads();
    if(t==0){
      #pragma unroll
      for(int mi=0;mi<8;mi++){
        float ss=0.f;
        #pragma unroll
        for(int i=0;i<8;i++) ss+=exs[mi*8+i];
        float inv=1.f/ss;
        #pragma unroll
        for(int i=0;i<8;i++) al[mi*8+i]=exs[mi*8+i]*inv;
      }
    }
    __syncthreads();
    {
      int half=t>>7, tt=t&127;
      #pragma unroll
      for(int q=0;q<4;q++){
        int mi=half*4+q;
        int m=m0+mi;
        if(m<Mtot){
          float a2=0.f;
          #pragma unroll
          for(int i=0;i<8;i++) a2+=al[mi*8+i]*nv[(mi*8+i)*128+tt];
          g_NG0[((size_t)b*Mtot+m)*128+tt]=a2;
        }
      }
    }
    __syncthreads();
  }
#undef ATTM_PRE
}

// -------- linear (concat 256 -> 128), persistent, FFMA2, double-buffered ---
__global__ void __launch_bounds__(256) k_lin(int nrows,int cfg,
    const int* __restrict__ idxtab,const float* __restrict__ extA,
    const float* __restrict__ extB,const float* __restrict__ w){
  extern __shared__ float sm[];
  float* ws=sm;          // 32768 [e][d]
  float* inT=sm+32768;   // 8192 [e][32]
  int t=threadIdx.x;
  for(int i=t;i<32768;i+=256) ws[i]=w[i];
  int ngroups=(nrows+31)>>5;
  float* outp=(cfg==0)?g_A0:(cfg==1)?g_A1:(cfg==2)?g_HG:g_NH;
  float pf[32];
  int grp=blockIdx.x;

#define LIN_LOAD_PF(GRP) do{ \
    int row0p=(GRP)*32; \
    _Pragma("unroll") \
    for(int k=0;k<32;k++){ \
      int i=t+k*256; int r=i&31,e=i>>5,row=row0p+r; \
      float v=0.f; \
      if(row<nrows){ \
        if(e<128){ \
          if(cfg==0)      v=extA[(size_t)idxtab[row]*128+e]; \
          else if(cfg==1) v=extA[(size_t)g_IN1[row]*128+e]; \
          else if(cfg==2) v=g_A0[(size_t)row*128+e]; \
          else            v=extA[(size_t)(row%50)*128+e]; \
        }else{ \
          int e2=e-128; \
          if(cfg==0)      v=g_NG0[(size_t)row*128+e2]; \
          else if(cfg==1) v=g_NG1[(size_t)row*128+e2]; \
          else if(cfg==2) v=g_NG0[(size_t)row*128+e2]; \
          else            v=extB[(size_t)row*128+e2]; \
        } \
      } \
      pf[k]=v; \
    } \
  }while(0)

  if(grp<ngroups) LIN_LOAD_PF(grp);
  for(;grp<ngroups;grp+=gridDim.x){
    __syncthreads();
    #pragma unroll
    for(int k=0;k<32;k++) inT[t+k*256]=pf[k];
    __syncthreads();
    int nxt=grp+gridDim.x;
    if(nxt<ngroups) LIN_LOAD_PF(nxt);
    int row0=grp*32;
    int d=t&127,rh=t>>7;
    unsigned long long acc2[8];
    #pragma unroll
    for(int q=0;q<8;q++) acc2[q]=0ull;
    const ulonglong2* I8=(const ulonglong2*)inT;
    for(int e=0;e<256;e++){
      float wv=ws[e*128+d];
      unsigned long long wv2=f2pack(wv,wv);
      ulonglong2 u0=I8[e*8+rh*4+0];
      ulonglong2 u1=I8[e*8+rh*4+1];
      ulonglong2 u2=I8[e*8+rh*4+2];
      ulonglong2 u3=I8[e*8+rh*4+3];
      ffma2(acc2[0],wv2,u0.x); ffma2(acc2[1],wv2,u0.y);
      ffma2(acc2[2],wv2,u1.x); ffma2(acc2[3],wv2,u1.y);
      ffma2(acc2[4],wv2,u2.x); ffma2(acc2[5],wv2,u2.y);
      ffma2(acc2[6],wv2,u3.x); ffma2(acc2[7],wv2,u3.y);
    }
    #pragma unroll
    for(int q=0;q<8;q++){
      float lo,hi;
      f2unpack(acc2[q],lo,hi);
      int rlo=row0+rh*16+q*2;
      if(rlo<nrows){
        float v=(cfg==3)?tanhf(lo):fmaxf(lo,0.f);
        outp[(size_t)rlo*128+d]=v;
      }
      if(rlo+1<nrows){
        float v=(cfg==3)?tanhf(hi):fmaxf(hi,0.f);
        outp[(size_t)(rlo+1)*128+d]=v;
      }
    }
  }
#undef LIN_LOAD_PF
}

// ---------------- mix / ssl ----------------
__global__ void k_mix(float* __restrict__ out){
  int i=blockIdx.x*blockDim.x+threadIdx.x;
  if(i<819200) out[i]=g_HL[i]+g_HG[i];
}
__global__ void k_ssl(){
  __shared__ float red[128];
  int b=blockIdx.x,t=threadIdx.x;
  int pb=g_PR[b];
  float pos=0.f,neg=0.f;
  for(int l=0;l<50;l++){
    float hl=g_HL[(size_t)b*6400+l*128+t];
    float hg=g_HG[(size_t)b*6400+l*128+t];
    pos+=hl*hg;
    neg+=hg*g_HL[(size_t)pb*6400+g_PC[l]*128+t];
  }
  float sp=1.f/(1.f+expf(-pos)),sn=1.f/(1.f+expf(-neg));
  float term=-logf(1e-8f+sp)-logf(1e-8f+1.f-sn);
  red[t]=term; __syncthreads();
  for(int o=64;o;o>>=1){ if(t<o) red[t]+=red[t+o]; __syncthreads(); }
  if(t==0) g_LP[b]=red[0];
}
__global__ void k_fin(float* __restrict__ out){
  __shared__ float r[128];
  int t=threadIdx.x;
  r[t]=g_LP[t]; __syncthreads();
  for(int o=64;o;o>>=1){ if(t<o) r[t]+=r[t+o]; __syncthreads(); }
  if(t==0) out[819200]=0.005f*r[0];
}

// ---------------- glu/select ----------------
__global__ void __launch_bounds__(256) k_glu(const float* __restrict__ hidden,
    const int* __restrict__ mask,const float* __restrict__ glu1w,
    const float* __restrict__ glu1b,const float* __restrict__ glu2w,
    const float* __restrict__ w2){
  extern __shared__ float sm[];
  float* g1t=sm;        // 16384 [e][d]
  float* hS =sm+16384;  // 6400
  float* nhS=sm+22784;  // 6400
  float* hs =sm+29184;  // 128
  float* t2 =sm+29312;  // 128
  float* bet=sm+29440;  // 64
  float* w2s=sm+29504;  // 128
  float* b1s=sm+29632;  // 128
  int b=blockIdx.x,t=threadIdx.x,warp=t>>5,lane=t&31;
  for(int i=t;i<16384;i+=256){ int e=i>>7,d=i&127; g1t[i]=glu1w[d*128+e]; }
  for(int i=t;i<6400;i+=256){ hS[i]=hidden[(size_t)b*6400+i]; nhS[i]=g_NH[(size_t)b*6400+i]; }
  if(t<128){ w2s[t]=w2[t]; b1s[t]=glu1b[t]; }
  __syncthreads();
  if(t<128){
    float a=0.f,ms=0.f;
    for(int l=0;l<50;l++){ float mv=(float)mask[b*50+l]; a+=hS[l*128+t]*mv; ms+=mv; }
    hs[t]=a/ms;
  }
  __syncthreads();
  if(t<128){
    float a=0.f;
    for(int e=0;e<128;e++) a+=hs[e]*glu2w[t*128+e];
    t2[t]=a;
  }
  __syncthreads();
  const float4* G14=(const float4*)g1t;
  for(int lb=0;lb<56;lb+=8){
    int l=lb+warp;
    if(l<50){
      const float4* N4=(const float4*)(nhS+l*128);
      float a0=0,a1=0,a2=0,a3=0;
      #pragma unroll 4
      for(int e4=0;e4<32;e4++){
        float4 a=N4[e4];
        float4 w=G14[(e4*4+0)*32+lane];
        a0+=a.x*w.x; a1+=a.x*w.y; a2+=a.x*w.z; a3+=a.x*w.w;
        w=G14[(e4*4+1)*32+lane];
        a0+=a.y*w.x; a1+=a.y*w.y; a2+=a.y*w.z; a3+=a.y*w.w;
        w=G14[(e4*4+2)*32+lane];
        a0+=a.z*w.x; a1+=a.z*w.y; a2+=a.z*w.z; a3+=a.z*w.w;
        w=G14[(e4*4+3)*32+lane];
        a0+=a.w*w.x; a1+=a.w*w.y; a2+=a.w*w.z; a3+=a.w*w.w;
      }
      int d0=lane*4;
      a0=1.f/(1.f+expf(-(a0+b1s[d0]+t2[d0])));
      a1=1.f/(1.f+expf(-(a1+b1s[d0+1]+t2[d0+1])));
      a2=1.f/(1.f+expf(-(a2+b1s[d0+2]+t2[d0+2])));
      a3=1.f/(1.f+expf(-(a3+b1s[d0+3]+t2[d0+3])));
      float p=a0*w2s[d0]+a1*w2s[d0+1]+a2*w2s[d0+2]+a3*w2s[d0+3];
      for(int o=16;o;o>>=1) p+=__shfl_xor_sync(0xffffffffu,p,o);
      if(lane==0) bet[l]=p*(float)mask[b*50+l];
    }
  }
  __syncthreads();
  if(t<128){
    float a=0.f;
    for(int l=0;l<50;l++) a+=bet[l]*hS[l*128+t];
    g_SEL[b*128+t]=a;
  }
}

// ---------------- neighbor top-k ----------------
__global__ void __launch_bounds__(128) k_nbr(){
  extern __shared__ float sm[];
  float* sel=sm;  // 16384
  __shared__ float nrm[128];
  __shared__ float ev[128];
  __shared__ float tv[9];
  __shared__ int   ti[9];
  __shared__ float red[4];
  int b=blockIdx.x,t=threadIdx.x;
  for(int i=t;i<16384;i+=128) sel[i]=g_SEL[i];
  __syncthreads();
  { float a=0.f;
    for(int d=0;d<128;d++){ float v=sel[t*128+d]; a+=v*v; }
    nrm[t]=sqrtf(a+128e-6f); }
  __syncthreads();
  float dot=0.f;
  for(int d=0;d<128;d++) dot+=sel[b*128+d]*sel[t*128+d];
  float e=dot/(nrm[b]*nrm[t]);
  float mx=e;
  for(int o=16;o;o>>=1) mx=fmaxf(mx,__shfl_xor_sync(0xffffffffu,mx,o));
  if((t&31)==0) red[t>>5]=mx;
  __syncthreads();
  mx=fmaxf(fmaxf(red[0],red[1]),fmaxf(red[2],red[3]));
  float ex=expf(e-mx);
  float ss=ex;
  for(int o=16;o;o>>=1) ss+=__shfl_xor_sync(0xffffffffu,ss,o);
  __syncthreads();
  if((t&31)==0) red[t>>5]=ss;
  __syncthreads();
  ss=red[0]+red[1]+red[2]+red[3];
  ev[t]=ex/ss;
  __syncthreads();
  if(t==0){
    for(int k=0;k<9;k++){
      float bv=-1.f; int bi=0;
      for(int j=0;j<128;j++) if(ev[j]>bv){ bv=ev[j]; bi=j; }
      tv[k]=bv; ti[k]=bi; ev[bi]=-2.f;
    }
    float m2=tv[0],s2=0.f;
    for(int k=0;k<9;k++){ tv[k]=expf(tv[k]-m2); s2+=tv[k]; }
    float inv=1.f/s2;
    for(int k=0;k<9;k++) tv[k]*=inv;
  }
  __syncthreads();
  float nb=0.f;
  #pragma unroll
  for(int k=0;k<9;k++) nb+=tv[k]*sel[ti[k]*128+t];
  g_SEL2T[t*128+b]=sel[b*128+t]+nb;
}

// ---------------- scores GEMM (FFMA2) ----------------
__global__ void __launch_bounds__(256) k_scores(const float* __restrict__ emb,
                                                float* __restrict__ outp){
  extern __shared__ float sm[];
  float* selT=sm;        // 16384 [e][b]
  float* embT=sm+16384;  // 128*129 [e][j] stride 129
  int t=threadIdx.x;
  int j0=blockIdx.x*128;
  for(int i=t;i<16384;i+=256) selT[i]=g_SEL2T[i];
  for(int i=t;i<16384;i+=256){
    int j=i>>7,e=i&127;
    int node=1+j0+j;
    embT[e*129+j]=(node<100000)?emb[(size_t)node*128+e]:0.f;
  }
  __syncthreads();
  int j=t&127,bh=t>>7;
  unsigned long long acc2[32];
  #pragma unroll
  for(int q=0;q<32;q++) acc2[q]=0ull;
  const ulonglong2* S8=(const ulonglong2*)selT;
  for(int e=0;e<128;e++){
    float evv=embT[e*129+j];
    unsigned long long ev2=f2pack(evv,evv);
    const ulonglong2* s=&S8[e*32+bh*16];
    #pragma unroll
    for(int q=0;q<16;q++){
      ulonglong2 u=s[q];
      ffma2(acc2[q*2+0],ev2,u.x);
      ffma2(acc2[q*2+1],ev2,u.y);
    }
  }
  if(j0+j<99999){
    #pragma unroll
    for(int q=0;q<32;q++){
      float lo,hi;
      f2unpack(acc2[q],lo,hi);
      int b=bh*64+q*2;
      outp[(size_t)b*99999+j0+j]=lo;
      outp[(size_t)(b+1)*99999+j0+j]=hi;
    }
  }
}

// ---------------- launch ----------------
extern "C" void kernel_launch(void* const* d_in,const int* in_sizes,int n_in,
                              void* d_out,int out_size){
  const int*   inputs =(const int*)d_in[0];
  const int*   adj    =(const int*)d_in[1];
  const int*   mask   =(const int*)d_in[2];
  const int*   item   =(const int*)d_in[3];
  const int*   adj_all=(const int*)d_in[5];
  const float* num_w  =(const float*)d_in[6];
  const float* emb    =(const float*)d_in[7];
  const float* pos    =(const float*)d_in[8];
  const float* a_local=(const float*)d_in[9];
  const float* gw1    =(const float*)d_in[10];
  const float* gw2    =(const float*)d_in[11];
  const float* gw3    =(const float*)d_in[12];
  const float* w1     =(const float*)d_in[13];
  const float* w2     =(const float*)d_in[14];
  const float* g1w    =(const float*)d_in[15];
  const float* g1b    =(const float*)d_in[16];
  const float* g2w    =(const float*)d_in[17];
  float* out=(float*)d_out;

  const size_t SM_ATT=25088u*4u;   // 100,352 B -> 2 blocks/SM
  const size_t SM_LIN=40960u*4u;   // 163,840 B -> 1 block/SM
  const size_t SM_GLU=29760u*4u;
  const size_t SM_SC =32896u*4u;
  const size_t SM_NBR=16384u*4u;
  cudaFuncSetAttribute(k_att2,  cudaFuncAttributeMaxDynamicSharedMemorySize,(int)SM_ATT);
  cudaFuncSetAttribute(k_attm2, cudaFuncAttributeMaxDynamicSharedMemorySize,(int)SM_ATT);
  cudaFuncSetAttribute(k_lin,   cudaFuncAttributeMaxDynamicSharedMemorySize,(int)SM_LIN);
  cudaFuncSetAttribute(k_glu,   cudaFuncAttributeMaxDynamicSharedMemorySize,(int)SM_GLU);
  cudaFuncSetAttribute(k_scores,cudaFuncAttributeMaxDynamicSharedMemorySize,(int)SM_SC);
  cudaFuncSetAttribute(k_nbr,   cudaFuncAttributeMaxDynamicSharedMemorySize,(int)SM_NBR);

  k_prep1<<<200,256>>>(inputs,adj_all,num_w);
  k_prep2<<<1600,256>>>(adj_all,num_w);
  k_sess<<<128,128>>>(item,mask,emb);
  // hop 0: flattened mode0+mode1 attention (7296 chunks over 296 resident blocks)
  k_att2<<<296,256,SM_ATT>>>(25,emb,gw1,gw2);                        // -> g_NG0, g_NG1
  k_perm<<<1,128>>>();
  k_local<<<128,256>>>(inputs,adj,emb,a_local);
  k_lin<<<148,256,SM_LIN>>>(6400,0,inputs,emb,0,gw3);                // -> g_A0
  k_lin<<<148,256,SM_LIN>>>(51200,1,0,emb,0,gw3);                    // -> g_A1
  // hop 1 (896 chunks over 224 blocks = 1 wave)
  k_attm2<<<224,256,SM_ATT>>>(4,gw1+129*128,gw2+128);                // -> g_NG0
  k_lin<<<148,256,SM_LIN>>>(6400,2,0,0,0,gw3+256*128);               // -> g_HG
  // outputs
  k_mix<<<3200,256>>>(out);
  k_ssl<<<128,128>>>();
  k_fin<<<1,128>>>(out);
  // scores head
  k_lin<<<148,256,SM_LIN>>>(6400,3,0,pos,out,w1);                    // -> g_NH
  k_glu<<<128,256,SM_GLU>>>(out,mask,g1w,g1b,g2w,w2);
  k_nbr<<<128,128,SM_NBR>>>();
  k_scores<<<782,256,SM_SC>>>(emb,out+819201);
}

// round 13
// speedup vs baseline: 2.3262x; 1.0314x over previous
#include <cuda_runtime.h>
#include <math.h>

// ---------------- f32x2 packed-FMA helpers (bitwise = 2x IEEE fp32 FMA) ----
__device__ __forceinline__ unsigned long long f2pack(float x,float y){
  unsigned long long r;
  asm("mov.b64 %0,{%1,%2};":"=l"(r):"r"(__float_as_uint(x)),"r"(__float_as_uint(y)));
  return r;
}
__device__ __forceinline__ void f2unpack(unsigned long long v,float&x,float&y){
  unsigned ux,uy;
  asm("mov.b64 {%0,%1},%2;":"=r"(ux),"=r"(uy):"l"(v));
  x=__uint_as_float(ux); y=__uint_as_float(uy);
}
__device__ __forceinline__ void ffma2(unsigned long long&d,unsigned long long a,unsigned long long b){
  asm("fma.rn.f32x2 %0,%1,%2,%0;":"+l"(d):"l"(a),"l"(b));
}

// ---------------- scratch ----------------
__device__ float g_SESS[128*128];
__device__ int   g_IN1[128*400];
__device__ float g_W0 [128*400];
__device__ int   g_IN2[128*3200];
__device__ float g_W1n[128*3200];
__device__ float g_NG0[128*50*128];
__device__ float g_NG1[128*400*128];
__device__ float g_A0 [128*50*128];
__device__ float g_A1 [128*400*128];
__device__ float g_HL [128*50*128];
__device__ float g_HG [128*50*128];
__device__ float g_NH [128*50*128];
__device__ float g_SEL[128*128];
__device__ float g_SEL2T[128*128];
__device__ float g_LP[128];
__device__ int   g_PR[128];
__device__ int   g_PC[64];

// ---------------- threefry ----------------
__device__ __forceinline__ void tf(unsigned k0,unsigned k1,unsigned x0,unsigned x1,
                                   unsigned&o0,unsigned&o1){
  unsigned ks2=k0^k1^0x1BD11BDAu;
  x0+=k0; x1+=k1;
#define RND(r) {x0+=x1; x1=(x1<<(r))|(x1>>(32-(r))); x1^=x0;}
  RND(13)RND(15)RND(26)RND(6)   x0+=k1;  x1+=ks2+1u;
  RND(17)RND(29)RND(16)RND(24)  x0+=ks2; x1+=k0+2u;
  RND(13)RND(15)RND(26)RND(6)   x0+=k0;  x1+=k1+3u;
  RND(17)RND(29)RND(16)RND(24)  x0+=k1;  x1+=ks2+4u;
  RND(13)RND(15)RND(26)RND(6)   x0+=ks2; x1+=k0+5u;
#undef RND
  o0=x0; o1=x1;
}

__global__ void k_perm(){
  __shared__ unsigned keys[4];
  __shared__ unsigned br[128];
  __shared__ unsigned bc[64];
  int t=threadIdx.x;
  if(t==0){
    unsigned u0,u1,v0,v1,p0,p1,q0,q1;
    tf(0u,42u,0u,2u,u0,u1); tf(0u,42u,1u,3u,v0,v1);
    unsigned kr0=u0,kr1=v0,kc0=u1,kc1=v1;
    tf(kr0,kr1,0u,2u,p0,p1); tf(kr0,kr1,1u,3u,q0,q1);
    keys[0]=p1; keys[1]=q1;
    tf(kc0,kc1,0u,2u,p0,p1); tf(kc0,kc1,1u,3u,q0,q1);
    keys[2]=p1; keys[3]=q1;
  }
  __syncthreads();
  { int j=t&63; unsigned w0,w1;
    tf(keys[0],keys[1],(unsigned)j,(unsigned)(j+64),w0,w1);
    br[t]=(t<64)?w0:w1; }
  if(t<50){ int j=(t<25)?t:t-25; unsigned w0,w1;
    tf(keys[2],keys[3],(unsigned)j,(unsigned)(j+25),w0,w1);
    bc[t]=(t<25)?w0:w1; }
  __syncthreads();
  { unsigned mine=br[t]; int r=0;
    for(int j=0;j<128;j++){ unsigned bj=br[j]; r+=(bj<mine)||(bj==mine&&j<t); }
    g_PR[r]=t; }
  if(t<50){ unsigned mine=bc[t]; int r=0;
    for(int j=0;j<50;j++){ unsigned bj=bc[j]; r+=(bj<mine)||(bj==mine&&j<t); }
    g_PC[r]=t; }
}

// ---------------- prep ----------------
__global__ void k_prep1(const int* __restrict__ inputs,const int* __restrict__ adj_all,
                        const float* __restrict__ num_w){
  int t=blockIdx.x*blockDim.x+threadIdx.x;
  if(t<128*400){
    int b=t/400,m=t%400;
    int node=inputs[b*50+(m>>3)];
    g_IN1[t]=adj_all[node*8+(m&7)];
    g_W0[t]=num_w[node*8+(m&7)];
  }
}
__global__ void k_prep2(const int* __restrict__ adj_all,const float* __restrict__ num_w){
  int t=blockIdx.x*blockDim.x+threadIdx.x;
  if(t<128*3200){
    int b=t/3200,m=t%3200;
    int node=g_IN1[b*400+(m>>3)];
    g_IN2[t]=adj_all[node*8+(m&7)];
    g_W1n[t]=num_w[node*8+(m&7)];
  }
}
__global__ void k_sess(const int* __restrict__ item,const int* __restrict__ mask,
                       const float* __restrict__ emb){
  int b=blockIdx.x,d=threadIdx.x;
  float acc=0.f,ms=0.f;
  for(int l=0;l<50;l++){
    float mv=(float)mask[b*50+l];
    acc+=emb[(size_t)item[b*50+l]*128+d]*mv; ms+=mv;
  }
  g_SESS[b*128+d]=acc/ms;
}

// ---------------- local agg ----------------
__global__ void __launch_bounds__(256) k_local(const int* __restrict__ inputs,
    const int* __restrict__ adj,const float* __restrict__ emb,
    const float* __restrict__ a_local){
  __shared__ float hs[6400];
  __shared__ float al[512];
  __shared__ float hik[512];
  __shared__ float es[50];
  __shared__ float att[50];
  int b=blockIdx.x,t=threadIdx.x,warp=t>>5,lane=t&31;
  for(int i=t;i<6400;i+=256) hs[i]=emb[(size_t)inputs[b*50+(i>>7)]*128+(i&127)];
  for(int i=t;i<512;i+=256) al[i]=a_local[i];
  __syncthreads();
  for(int ii=0;ii<50;ii++){
    if(t<128){
      float hv=hs[ii*128+t];
      #pragma unroll
      for(int k=0;k<4;k++) hik[k*128+t]=hv*al[k*128+t];
    }
    __syncthreads();
    for(int jj=warp;jj<50;jj+=8){
      int aj=adj[b*2500+ii*50+jj];
      int k=aj>0?aj-1:0;
      const float4* hk=(const float4*)(hik+k*128);
      const float4* hj=(const float4*)(hs+jj*128);
      float4 p=hk[lane],q=hj[lane];
      float v=p.x*q.x+p.y*q.y+p.z*q.z+p.w*q.w;
      for(int o=16;o;o>>=1) v+=__shfl_xor_sync(0xffffffffu,v,o);
      float e=(aj>0)?(v>0.f?v:0.2f*v):-9e15f;
      if(lane==0) es[jj]=e;
    }
    __syncthreads();
    if(warp==0){
      float m1=-3.4e38f;
      for(int j=lane;j<50;j+=32) m1=fmaxf(m1,es[j]);
      for(int o=16;o;o>>=1) m1=fmaxf(m1,__shfl_xor_sync(0xffffffffu,m1,o));
      float ss=0.f;
      for(int j=lane;j<50;j+=32){ float ex=expf(es[j]-m1); att[j]=ex; ss+=ex; }
      for(int o=16;o;o>>=1) ss+=__shfl_xor_sync(0xffffffffu,ss,o);
      float inv=1.f/ss;
      for(int j=lane;j<50;j+=32) att[j]*=inv;
    }
    __syncthreads();
    if(t<128){
      float acc=0.f;
      for(int j=0;j<50;j++) acc+=att[j]*hs[j*128+t];
      g_HL[(size_t)b*6400+ii*128+t]=acc;
    }
    __syncthreads();
  }
}

// ===== attention core: warp w <-> row m0+w, all 8 samples warp-local =======
// Zero per-chunk block barriers; softmax fully in registers; arithmetic
// chains bitwise-identical to R9/R12.
#define ATT_COMPUTE(NWP,OUTNG,MTOT)                                            \
  {                                                                            \
    __syncwarp();                                                              \
    unsigned long long acc2[8][2];                                             \
    _Pragma("unroll")                                                          \
    for(int ss=0;ss<8;ss++){ acc2[ss][0]=0ull; acc2[ss][1]=0ull; }             \
    for(int e4=0;e4<32;e4++){                                                  \
      ulonglong2 w0 =WT8[(e4*4+0)*32+lane];                                    \
      ulonglong2 w1v=WT8[(e4*4+1)*32+lane];                                    \
      ulonglong2 w2v=WT8[(e4*4+2)*32+lane];                                    \
      ulonglong2 w3v=WT8[(e4*4+3)*32+lane];                                    \
      _Pragma("unroll")                                                        \
      for(int ss=0;ss<8;ss++){                                                 \
        float4 a=NV4[(w*8+ss)*32+e4];                                          \
        unsigned long long ax=f2pack(a.x,a.x);                                 \
        unsigned long long ay=f2pack(a.y,a.y);                                 \
        unsigned long long az=f2pack(a.z,a.z);                                 \
        unsigned long long aw=f2pack(a.w,a.w);                                 \
        ffma2(acc2[ss][0],ax,w0.x);  ffma2(acc2[ss][1],ax,w0.y);               \
        ffma2(acc2[ss][0],ay,w1v.x); ffma2(acc2[ss][1],ay,w1v.y);              \
        ffma2(acc2[ss][0],az,w2v.x); ffma2(acc2[ss][1],az,w2v.y);              \
        ffma2(acc2[ss][0],aw,w3v.x); ffma2(acc2[ss][1],aw,w3v.y);              \
      }                                                                        \
    }                                                                          \
    int d0=lane*4;                                                             \
    size_t base8=((size_t)b*MTOT+mclamp)*8;                                    \
    float pr[8];                                                               \
    _Pragma("unroll")                                                          \
    for(int ss=0;ss<8;ss++){                                                   \
      float a0,a1,a2,a3;                                                       \
      f2unpack(acc2[ss][0],a0,a1);                                             \
      f2unpack(acc2[ss][1],a2,a3);                                             \
      float nwv=NWP[base8+ss];                                                 \
      float v0=a0+nwv*w129[d0];                                                \
      float v1=a1+nwv*w129[d0+1];                                              \
      float v2=a2+nwv*w129[d0+2];                                              \
      float v3=a3+nwv*w129[d0+3];                                              \
      v0=v0>0.f?v0:0.2f*v0; v1=v1>0.f?v1:0.2f*v1;                              \
      v2=v2>0.f?v2:0.2f*v2; v3=v3>0.f?v3:0.2f*v3;                              \
      float p=v0*g2[d0]+v1*g2[d0+1]+v2*g2[d0+2]+v3*g2[d0+3];                   \
      for(int o=16;o;o>>=1) p+=__shfl_xor_sync(0xffffffffu,p,o);               \
      pr[ss]=p;                                                                \
    }                                                                          \
    float mx=pr[0];                                                            \
    _Pragma("unroll")                                                          \
    for(int i=1;i<8;i++) mx=fmaxf(mx,pr[i]);                                   \
    float exr[8];                                                              \
    _Pragma("unroll")                                                          \
    for(int i=0;i<8;i++) exr[i]=expf(pr[i]-mx);                                \
    float ssum=0.f;                                                            \
    _Pragma("unroll")                                                          \
    for(int i=0;i<8;i++) ssum+=exr[i];                                         \
    float inv=1.f/ssum;                                                        \
    if(m0+w<MTOT){                                                             \
      float o0=0.f,o1=0.f,o2=0.f,o3=0.f;                                       \
      _Pragma("unroll")                                                        \
      for(int i=0;i<8;i++){                                                    \
        float ali=exr[i]*inv;                                                  \
        float4 r=NV4[(w*8+i)*32+lane];                                         \
        o0+=ali*r.x; o1+=ali*r.y; o2+=ali*r.z; o3+=ali*r.w;                    \
      }                                                                        \
      float4 ov; ov.x=o0; ov.y=o1; ov.z=o2; ov.w=o3;                           \
      ((float4*)OUTNG)[((size_t)b*MTOT+(m0+w))*32+lane]=ov;                    \
    }                                                                          \
  }

// ---------------- hop-0 global attention: flattened queue ------------------
__global__ void __launch_bounds__(256) k_att2(int Q,
    const float* __restrict__ emb,const float* __restrict__ gw1h,
    const float* __restrict__ gw2h){
  extern __shared__ float sm[];
  float* wt  = sm;         // 16384 [e][d]
  float* nv  = sm+16384;   // 8192 : 64 rows of 128
  float* w129= sm+24576;   // 128
  float* g2  = sm+24704;   // 128
  int t=threadIdx.x,lane=t&31,w=t>>5;
  if(t<128){ w129[t]=gw1h[16384+t]; g2[t]=gw2h[t]; }
  __syncthreads();
  const ulonglong2* WT8=(const ulonglong2*)wt;
  const float4* NV4=(const float4*)nv;
  int g0=blockIdx.x*Q, g1=min(g0+Q,7296);
  int cur_b=-1;
  float4 pfv[8];
#define ATT2_PRE(G) do{ \
    int bb=(G)/57, cc=(G)-bb*57; \
    int is1p=(cc>=7); \
    int Mt=is1p?400:50; \
    int mm0=(is1p?(cc-7):cc)*8; \
    const int* ni=is1p?g_IN2:g_IN1; \
    int mp=min(mm0+w,Mt-1); \
    size_t bp=((size_t)bb*Mt+mp)*8; \
    _Pragma("unroll") \
    for(int ss=0;ss<8;ss++) \
      pfv[ss]=((const float4*)emb)[(size_t)ni[bp+ss]*32+lane]; \
  }while(0)
  if(g0<g1) ATT2_PRE(g0);
  for(int g=g0;g<g1;g++){
    int b=g/57, c=g-b*57;
    if(b!=cur_b){
      __syncthreads();
      for(int i=t;i<16384;i+=256) wt[i]=g_SESS[b*128+(i>>7)]*gw1h[i];
      cur_b=b;
      __syncthreads();
    }
    int is1=(c>=7);
    int Mtot=is1?400:50;
    int m0=(is1?(c-7):c)*8;
    const float* nwp = is1?g_W1n:g_W0;
    float* outNG = is1?g_NG1:g_NG0;
    int mclamp=min(m0+w,Mtot-1);
    #pragma unroll
    for(int ss=0;ss<8;ss++)
      ((float4*)nv)[(w*8+ss)*32+lane]=pfv[ss];
    if(g+1<g1) ATT2_PRE(g+1);
    ATT_COMPUTE(nwp,outNG,Mtot)
  }
#undef ATT2_PRE
}

// ---------------- hop-1 attention (src = g_A1 rows) -------------------------
__global__ void __launch_bounds__(256) k_attm2(int Q,
    const float* __restrict__ gw1h,const float* __restrict__ gw2h){
  extern __shared__ float sm[];
  float* wt  = sm;
  float* nv  = sm+16384;
  float* w129= sm+24576;
  float* g2  = sm+24704;
  int t=threadIdx.x,lane=t&31,w=t>>5;
  if(t<128){ w129[t]=gw1h[16384+t]; g2[t]=gw2h[t]; }
  __syncthreads();
  const ulonglong2* WT8=(const ulonglong2*)wt;
  const float4* NV4=(const float4*)nv;
  int g0=blockIdx.x*Q, g1=min(g0+Q,896);
  int cur_b=-1;
  float4 pfv[8];
#define ATTM_PRE(G) do{ \
    int bb=(G)/7, cc=(G)-bb*7; \
    int mp=min(cc*8+w,49); \
    size_t bp=((size_t)bb*50+mp)*8; \
    _Pragma("unroll") \
    for(int ss=0;ss<8;ss++) \
      pfv[ss]=((const float4*)g_A1)[(bp+ss)*32+lane]; \
  }while(0)
  if(g0<g1) ATTM_PRE(g0);
  for(int g=g0;g<g1;g++){
    int b=g/7, c=g-b*7;
    if(b!=cur_b){
      __syncthreads();
      for(int i=t;i<16384;i+=256) wt[i]=g_SESS[b*128+(i>>7)]*gw1h[i];
      cur_b=b;
      __syncthreads();
    }
    const int Mtot=50;
    int m0=c*8;
    int mclamp=min(m0+w,Mtot-1);
    #pragma unroll
    for(int ss=0;ss<8;ss++)
      ((float4*)nv)[(w*8+ss)*32+lane]=pfv[ss];
    if(g+1<g1) ATTM_PRE(g+1);
    ATT_COMPUTE(g_W0,g_NG0,Mtot)
  }
#undef ATTM_PRE
}

// -------- linear (concat 256 -> 128), persistent, FFMA2, double-buffered ---
__global__ void __launch_bounds__(256) k_lin(int nrows,int cfg,
    const int* __restrict__ idxtab,const float* __restrict__ extA,
    const float* __restrict__ extB,const float* __restrict__ w){
  extern __shared__ float sm[];
  float* ws=sm;          // 32768 [e][d]
  float* inT=sm+32768;   // 8192 [e][32]
  int t=threadIdx.x;
  for(int i=t;i<32768;i+=256) ws[i]=w[i];
  int ngroups=(nrows+31)>>5;
  float* outp=(cfg==0)?g_A0:(cfg==1)?g_A1:(cfg==2)?g_HG:g_NH;
  float pf[32];
  int grp=blockIdx.x;

#define LIN_LOAD_PF(GRP) do{ \
    int row0p=(GRP)*32; \
    _Pragma("unroll") \
    for(int k=0;k<32;k++){ \
      int i=t+k*256; int r=i&31,e=i>>5,row=row0p+r; \
      float v=0.f; \
      if(row<nrows){ \
        if(e<128){ \
          if(cfg==0)      v=extA[(size_t)idxtab[row]*128+e]; \
          else if(cfg==1) v=extA[(size_t)g_IN1[row]*128+e]; \
          else if(cfg==2) v=g_A0[(size_t)row*128+e]; \
          else            v=extA[(size_t)(row%50)*128+e]; \
        }else{ \
          int e2=e-128; \
          if(cfg==0)      v=g_NG0[(size_t)row*128+e2]; \
          else if(cfg==1) v=g_NG1[(size_t)row*128+e2]; \
          else if(cfg==2) v=g_NG0[(size_t)row*128+e2]; \
          else            v=extB[(size_t)row*128+e2]; \
        } \
      } \
      pf[k]=v; \
    } \
  }while(0)

  if(grp<ngroups) LIN_LOAD_PF(grp);
  for(;grp<ngroups;grp+=gridDim.x){
    __syncthreads();
    #pragma unroll
    for(int k=0;k<32;k++) inT[t+k*256]=pf[k];
    __syncthreads();
    int nxt=grp+gridDim.x;
    if(nxt<ngroups) LIN_LOAD_PF(nxt);
    int row0=grp*32;
    int d=t&127,rh=t>>7;
    unsigned long long acc2[8];
    #pragma unroll
    for(int q=0;q<8;q++) acc2[q]=0ull;
    const ulonglong2* I8=(const ulonglong2*)inT;
    for(int e=0;e<256;e++){
      float wv=ws[e*128+d];
      unsigned long long wv2=f2pack(wv,wv);
      ulonglong2 u0=I8[e*8+rh*4+0];
      ulonglong2 u1=I8[e*8+rh*4+1];
      ulonglong2 u2=I8[e*8+rh*4+2];
      ulonglong2 u3=I8[e*8+rh*4+3];
      ffma2(acc2[0],wv2,u0.x); ffma2(acc2[1],wv2,u0.y);
      ffma2(acc2[2],wv2,u1.x); ffma2(acc2[3],wv2,u1.y);
      ffma2(acc2[4],wv2,u2.x); ffma2(acc2[5],wv2,u2.y);
      ffma2(acc2[6],wv2,u3.x); ffma2(acc2[7],wv2,u3.y);
    }
    #pragma unroll
    for(int q=0;q<8;q++){
      float lo,hi;
      f2unpack(acc2[q],lo,hi);
      int rlo=row0+rh*16+q*2;
      if(rlo<nrows){
        float v=(cfg==3)?tanhf(lo):fmaxf(lo,0.f);
        outp[(size_t)rlo*128+d]=v;
      }
      if(rlo+1<nrows){
        float v=(cfg==3)?tanhf(hi):fmaxf(hi,0.f);
        outp[(size_t)(rlo+1)*128+d]=v;
      }
    }
  }
#undef LIN_LOAD_PF
}

// ---------------- mix / ssl ----------------
__global__ void k_mix(float* __restrict__ out){
  int i=blockIdx.x*blockDim.x+threadIdx.x;
  if(i<819200) out[i]=g_HL[i]+g_HG[i];
}
__global__ void k_ssl(){
  __shared__ float red[128];
  int b=blockIdx.x,t=threadIdx.x;
  int pb=g_PR[b];
  float pos=0.f,neg=0.f;
  for(int l=0;l<50;l++){
    float hl=g_HL[(size_t)b*6400+l*128+t];
    float hg=g_HG[(size_t)b*6400+l*128+t];
    pos+=hl*hg;
    neg+=hg*g_HL[(size_t)pb*6400+g_PC[l]*128+t];
  }
  float sp=1.f/(1.f+expf(-pos)),sn=1.f/(1.f+expf(-neg));
  float term=-logf(1e-8f+sp)-logf(1e-8f+1.f-sn);
  red[t]=term; __syncthreads();
  for(int o=64;o;o>>=1){ if(t<o) red[t]+=red[t+o]; __syncthreads(); }
  if(t==0) g_LP[b]=red[0];
}
__global__ void k_fin(float* __restrict__ out){
  __shared__ float r[128];
  int t=threadIdx.x;
  r[t]=g_LP[t]; __syncthreads();
  for(int o=64;o;o>>=1){ if(t<o) r[t]+=r[t+o]; __syncthreads(); }
  if(t==0) out[819200]=0.005f*r[0];
}

// ---------------- glu/select ----------------
__global__ void __launch_bounds__(256) k_glu(const float* __restrict__ hidden,
    const int* __restrict__ mask,const float* __restrict__ glu1w,
    const float* __restrict__ glu1b,const float* __restrict__ glu2w,
    const float* __restrict__ w2){
  extern __shared__ float sm[];
  float* g1t=sm;        // 16384 [e][d]
  float* hS =sm+16384;  // 6400
  float* nhS=sm+22784;  // 6400
  float* hs =sm+29184;  // 128
  float* t2 =sm+29312;  // 128
  float* bet=sm+29440;  // 64
  float* w2s=sm+29504;  // 128
  float* b1s=sm+29632;  // 128
  int b=blockIdx.x,t=threadIdx.x,warp=t>>5,lane=t&31;
  for(int i=t;i<16384;i+=256){ int e=i>>7,d=i&127; g1t[i]=glu1w[d*128+e]; }
  for(int i=t;i<6400;i+=256){ hS[i]=hidden[(size_t)b*6400+i]; nhS[i]=g_NH[(size_t)b*6400+i]; }
  if(t<128){ w2s[t]=w2[t]; b1s[t]=glu1b[t]; }
  __syncthreads();
  if(t<128){
    float a=0.f,ms=0.f;
    for(int l=0;l<50;l++){ float mv=(float)mask[b*50+l]; a+=hS[l*128+t]*mv; ms+=mv; }
    hs[t]=a/ms;
  }
  __syncthreads();
  if(t<128){
    float a=0.f;
    for(int e=0;e<128;e++) a+=hs[e]*glu2w[t*128+e];
    t2[t]=a;
  }
  __syncthreads();
  const float4* G14=(const float4*)g1t;
  for(int lb=0;lb<56;lb+=8){
    int l=lb+warp;
    if(l<50){
      const float4* N4=(const float4*)(nhS+l*128);
      float a0=0,a1=0,a2=0,a3=0;
      #pragma unroll 4
      for(int e4=0;e4<32;e4++){
        float4 a=N4[e4];
        float4 w=G14[(e4*4+0)*32+lane];
        a0+=a.x*w.x; a1+=a.x*w.y; a2+=a.x*w.z; a3+=a.x*w.w;
        w=G14[(e4*4+1)*32+lane];
        a0+=a.y*w.x; a1+=a.y*w.y; a2+=a.y*w.z; a3+=a.y*w.w;
        w=G14[(e4*4+2)*32+lane];
        a0+=a.z*w.x; a1+=a.z*w.y; a2+=a.z*w.z; a3+=a.z*w.w;
        w=G14[(e4*4+3)*32+lane];
        a0+=a.w*w.x; a1+=a.w*w.y; a2+=a.w*w.z; a3+=a.w*w.w;
      }
      int d0=lane*4;
      a0=1.f/(1.f+expf(-(a0+b1s[d0]+t2[d0])));
      a1=1.f/(1.f+expf(-(a1+b1s[d0+1]+t2[d0+1])));
      a2=1.f/(1.f+expf(-(a2+b1s[d0+2]+t2[d0+2])));
      a3=1.f/(1.f+expf(-(a3+b1s[d0+3]+t2[d0+3])));
      float p=a0*w2s[d0]+a1*w2s[d0+1]+a2*w2s[d0+2]+a3*w2s[d0+3];
      for(int o=16;o;o>>=1) p+=__shfl_xor_sync(0xffffffffu,p,o);
      if(lane==0) bet[l]=p*(float)mask[b*50+l];
    }
  }
  __syncthreads();
  if(t<128){
    float a=0.f;
    for(int l=0;l<50;l++) a+=bet[l]*hS[l*128+t];
    g_SEL[b*128+t]=a;
  }
}

// ---------------- neighbor top-k ----------------
__global__ void __launch_bounds__(128) k_nbr(){
  extern __shared__ float sm[];
  float* sel=sm;  // 16384
  __shared__ float nrm[128];
  __shared__ float ev[128];
  __shared__ float tv[9];
  __shared__ int   ti[9];
  __shared__ float red[4];
  int b=blockIdx.x,t=threadIdx.x;
  for(int i=t;i<16384;i+=128) sel[i]=g_SEL[i];
  __syncthreads();
  { float a=0.f;
    for(int d=0;d<128;d++){ float v=sel[t*128+d]; a+=v*v; }
    nrm[t]=sqrtf(a+128e-6f); }
  __syncthreads();
  float dot=0.f;
  for(int d=0;d<128;d++) dot+=sel[b*128+d]*sel[t*128+d];
  float e=dot/(nrm[b]*nrm[t]);
  float mx=e;
  for(int o=16;o;o>>=1) mx=fmaxf(mx,__shfl_xor_sync(0xffffffffu,mx,o));
  if((t&31)==0) red[t>>5]=mx;
  __syncthreads();
  mx=fmaxf(fmaxf(red[0],red[1]),fmaxf(red[2],red[3]));
  float ex=expf(e-mx);
  float ss=ex;
  for(int o=16;o;o>>=1) ss+=__shfl_xor_sync(0xffffffffu,ss,o);
  __syncthreads();
  if((t&31)==0) red[t>>5]=ss;
  __syncthreads();
  ss=red[0]+red[1]+red[2]+red[3];
  ev[t]=ex/ss;
  __syncthreads();
  if(t==0){
    for(int k=0;k<9;k++){
      float bv=-1.f; int bi=0;
      for(int j=0;j<128;j++) if(ev[j]>bv){ bv=ev[j]; bi=j; }
      tv[k]=bv; ti[k]=bi; ev[bi]=-2.f;
    }
    float m2=tv[0],s2=0.f;
    for(int k=0;k<9;k++){ tv[k]=expf(tv[k]-m2); s2+=tv[k]; }
    float inv=1.f/s2;
    for(int k=0;k<9;k++) tv[k]*=inv;
  }
  __syncthreads();
  float nb=0.f;
  #pragma unroll
  for(int k=0;k<9;k++) nb+=tv[k]*sel[ti[k]*128+t];
  g_SEL2T[t*128+b]=sel[b*128+t]+nb;
}

// ---------------- scores GEMM (FFMA2) ----------------
__global__ void __launch_bounds__(256) k_scores(const float* __restrict__ emb,
                                                float* __restrict__ outp){
  extern __shared__ float sm[];
  float* selT=sm;        // 16384 [e][b]
  float* embT=sm+16384;  // 128*129 [e][j] stride 129
  int t=threadIdx.x;
  int j0=blockIdx.x*128;
  for(int i=t;i<16384;i+=256) selT[i]=g_SEL2T[i];
  for(int i=t;i<16384;i+=256){
    int j=i>>7,e=i&127;
    int node=1+j0+j;
    embT[e*129+j]=(node<100000)?emb[(size_t)node*128+e]:0.f;
  }
  __syncthreads();
  int j=t&127,bh=t>>7;
  unsigned long long acc2[32];
  #pragma unroll
  for(int q=0;q<32;q++) acc2[q]=0ull;
  const ulonglong2* S8=(const ulonglong2*)selT;
  for(int e=0;e<128;e++){
    float evv=embT[e*129+j];
    unsigned long long ev2=f2pack(evv,evv);
    const ulonglong2* s=&S8[e*32+bh*16];
    #pragma unroll
    for(int q=0;q<16;q++){
      ulonglong2 u=s[q];
      ffma2(acc2[q*2+0],ev2,u.x);
      ffma2(acc2[q*2+1],ev2,u.y);
    }
  }
  if(j0+j<99999){
    #pragma unroll
    for(int q=0;q<32;q++){
      float lo,hi;
      f2unpack(acc2[q],lo,hi);
      int b=bh*64+q*2;
      outp[(size_t)b*99999+j0+j]=lo;
      outp[(size_t)(b+1)*99999+j0+j]=hi;
    }
  }
}

// ---------------- launch ----------------
extern "C" void kernel_launch(void* const* d_in,const int* in_sizes,int n_in,
                              void* d_out,int out_size){
  const int*   inputs =(const int*)d_in[0];
  const int*   adj    =(const int*)d_in[1];
  const int*   mask   =(const int*)d_in[2];
  const int*   item   =(const int*)d_in[3];
  const int*   adj_all=(const int*)d_in[5];
  const float* num_w  =(const float*)d_in[6];
  const float* emb    =(const float*)d_in[7];
  const float* pos    =(const float*)d_in[8];
  const float* a_local=(const float*)d_in[9];
  const float* gw1    =(const float*)d_in[10];
  const float* gw2    =(const float*)d_in[11];
  const float* gw3    =(const float*)d_in[12];
  const float* w1     =(const float*)d_in[13];
  const float* w2     =(const float*)d_in[14];
  const float* g1w    =(const float*)d_in[15];
  const float* g1b    =(const float*)d_in[16];
  const float* g2w    =(const float*)d_in[17];
  float* out=(float*)d_out;

  const size_t SM_ATT=24832u*4u;   // 99,328 B -> 2 blocks/SM
  const size_t SM_LIN=40960u*4u;   // 163,840 B -> 1 block/SM
  const size_t SM_GLU=29760u*4u;
  const size_t SM_SC =32896u*4u;
  const size_t SM_NBR=16384u*4u;
  cudaFuncSetAttribute(k_att2,  cudaFuncAttributeMaxDynamicSharedMemorySize,(int)SM_ATT);
  cudaFuncSetAttribute(k_attm2, cudaFuncAttributeMaxDynamicSharedMemorySize,(int)SM_ATT);
  cudaFuncSetAttribute(k_lin,   cudaFuncAttributeMaxDynamicSharedMemorySize,(int)SM_LIN);
  cudaFuncSetAttribute(k_glu,   cudaFuncAttributeMaxDynamicSharedMemorySize,(int)SM_GLU);
  cudaFuncSetAttribute(k_scores,cudaFuncAttributeMaxDynamicSharedMemorySize,(int)SM_SC);
  cudaFuncSetAttribute(k_nbr,   cudaFuncAttributeMaxDynamicSharedMemorySize,(int)SM_NBR);

  k_prep1<<<200,256>>>(inputs,adj_all,num_w);
  k_prep2<<<1600,256>>>(adj_all,num_w);
  k_sess<<<128,128>>>(item,mask,emb);
  // hop 0: flattened mode0+mode1 attention (7296 chunks over 296 resident blocks)
  k_att2<<<296,256,SM_ATT>>>(25,emb,gw1,gw2);                        // -> g_NG0, g_NG1
  k_perm<<<1,128>>>();
  k_local<<<128,256>>>(inputs,adj,emb,a_local);
  k_lin<<<148,256,SM_LIN>>>(6400,0,inputs,emb,0,gw3);                // -> g_A0
  k_lin<<<148,256,SM_LIN>>>(51200,1,0,emb,0,gw3);                    // -> g_A1
  // hop 1 (896 chunks over 224 blocks = 1 wave)
  k_attm2<<<224,256,SM_ATT>>>(4,gw1+129*128,gw2+128);                // -> g_NG0
  k_lin<<<148,256,SM_LIN>>>(6400,2,0,0,0,gw3+256*128);               // -> g_HG
  // outputs
  k_mix<<<3200,256>>>(out);
  k_ssl<<<128,128>>>();
  k_fin<<<1,128>>>(out);
  // scores head
  k_lin<<<148,256,SM_LIN>>>(6400,3,0,pos,out,w1);                    // -> g_NH
  k_glu<<<128,256,SM_GLU>>>(out,mask,g1w,g1b,g2w,w2);
  k_nbr<<<128,128,SM_NBR>>>();
  k_scores<<<782,256,SM_SC>>>(emb,out+819201);
}